// round 13
// baseline (speedup 1.0000x reference)
#include <cuda_runtime.h>
#include <cuda_bf16.h>
#include <math.h>
#include <stdint.h>

#define BB   16
#define NN   512
#define DD   256
#define HH   8
#define DKK  32
#define CC   16
#define MTOT (BB*NN)   // 8192
typedef __nv_bfloat16 bf16;

// ---------------- scratch (device globals: no allocation allowed) ----------
__device__ __align__(16) bf16 g_emb_h[MTOT*DD],  g_emb_l[MTOT*DD];
__device__ __align__(16) bf16 g_gemb_h[MTOT*DD], g_gemb_l[MTOT*DD];
__device__ __align__(16) bf16 g_W_h[10*DD*DD],   g_W_l[10*DD*DD];
__device__ __align__(16) bf16 g_QKV_h[3*MTOT*DD], g_QKV_l[3*MTOT*DD];
__device__ __align__(16) bf16 g_pA_h[MTOT*DD],  g_pA_l[MTOT*DD];
__device__ __align__(16) bf16 g_pB_h[MTOT*DD],  g_pB_l[MTOT*DD];
__device__ float g_X32[MTOT*DD];
__device__ float g_topvec[BB*DD];
__device__ float g_P[BB*CC*DD];
__device__ float g_counts[BB*CC];

__device__ __forceinline__ float gelu_f(float x) {
    return 0.5f * x * (1.0f + erff(x * 0.7071067811865475f));
}

// ---------------- helpers ----------------------------------------------
__device__ __forceinline__ uint32_t smem_u32(const void* p) {
    return (uint32_t)__cvta_generic_to_shared(p);
}
__device__ __forceinline__ void cp16(void* dst, const void* src) {
    asm volatile("cp.async.cg.shared.global [%0], [%1], 16;"
                 :: "r"(smem_u32(dst)), "l"(src));
}
__device__ __forceinline__ void cp_commit() { asm volatile("cp.async.commit_group;"); }
template<int N> __device__ __forceinline__ void cp_wait() {
    asm volatile("cp.async.wait_group %0;" :: "n"(N));
}
__device__ __forceinline__ void ldsm_x4(uint32_t* r, uint32_t addr) {
    asm volatile("ldmatrix.sync.aligned.m8n8.x4.shared.b16 {%0,%1,%2,%3}, [%4];"
                 : "=r"(r[0]), "=r"(r[1]), "=r"(r[2]), "=r"(r[3]) : "r"(addr));
}
__device__ __forceinline__ void ldsm_x2(uint32_t* r, uint32_t addr) {
    asm volatile("ldmatrix.sync.aligned.m8n8.x2.shared.b16 {%0,%1}, [%2];"
                 : "=r"(r[0]), "=r"(r[1]) : "r"(addr));
}
__device__ __forceinline__ void ldsm_x2t(uint32_t* r, uint32_t addr) {
    asm volatile("ldmatrix.sync.aligned.m8n8.x2.trans.shared.b16 {%0,%1}, [%2];"
                 : "=r"(r[0]), "=r"(r[1]) : "r"(addr));
}
__device__ __forceinline__ void mma16816(float* d, const uint32_t* a, const uint32_t* b) {
    asm volatile(
        "mma.sync.aligned.m16n8k16.row.col.f32.bf16.bf16.f32 "
        "{%0,%1,%2,%3}, {%4,%5,%6,%7}, {%8,%9}, {%0,%1,%2,%3};"
        : "+f"(d[0]), "+f"(d[1]), "+f"(d[2]), "+f"(d[3])
        : "r"(a[0]), "r"(a[1]), "r"(a[2]), "r"(a[3]), "r"(b[0]), "r"(b[1]));
}
__device__ __forceinline__ void split_pack(float x, float y, uint32_t& hi, uint32_t& lo) {
    __nv_bfloat16 hx = __float2bfloat16(x);
    __nv_bfloat16 hy = __float2bfloat16(y);
    __nv_bfloat16 lx = __float2bfloat16(x - __bfloat162float(hx));
    __nv_bfloat16 ly = __float2bfloat16(y - __bfloat162float(hy));
    __nv_bfloat162 H(hx, hy), L(lx, ly);
    hi = *(uint32_t*)&H;
    lo = *(uint32_t*)&L;
}
__device__ __forceinline__ void split4(float4 v, uint2& h, uint2& l) {
    uint32_t h0, l0, h1, l1;
    split_pack(v.x, v.y, h0, l0);
    split_pack(v.z, v.w, h1, l1);
    h = make_uint2(h0, h1);
    l = make_uint2(l0, l1);
}

// ---------------- prep: split emb, gelu(emb), and 10 weights once ----------
#define EMB_QUADS (MTOT*DD/4)      // 524288
__global__ void __launch_bounds__(256) prep_k(
    const float* __restrict__ emb,
    const float* __restrict__ Wq0, const float* __restrict__ Wk0,
    const float* __restrict__ Wv0, const float* __restrict__ Wo0,
    const float* __restrict__ Wq1, const float* __restrict__ Wk1,
    const float* __restrict__ Wv1, const float* __restrict__ Wo1,
    const float* __restrict__ ffW1, const float* __restrict__ ffW2)
{
    int idx = blockIdx.x * 256 + threadIdx.x;
    if (idx < EMB_QUADS) {
        float4 v = ((const float4*)emb)[idx];
        uint2 h, l;
        split4(v, h, l);
        *(uint2*)(g_emb_h + idx*4) = h;
        *(uint2*)(g_emb_l + idx*4) = l;
        v.x = gelu_f(v.x); v.y = gelu_f(v.y); v.z = gelu_f(v.z); v.w = gelu_f(v.w);
        split4(v, h, l);
        *(uint2*)(g_gemb_h + idx*4) = h;
        *(uint2*)(g_gemb_l + idx*4) = l;
    } else {
        int w = idx - EMB_QUADS;
        int mat = w >> 14;          // 16384 quads per 256x256 matrix
        int off = w & 16383;
        const float* src;
        switch (mat) {
            case 0: src = Wq0; break;  case 1: src = Wk0; break;
            case 2: src = Wv0; break;  case 3: src = Wo0; break;
            case 4: src = Wq1; break;  case 5: src = Wk1; break;
            case 6: src = Wv1; break;  case 7: src = Wo1; break;
            case 8: src = ffW1 + DD*DD; break;   // bottom half of ff_W1
            default: src = ffW2; break;
        }
        float4 v = ((const float4*)src)[off];
        uint2 h, l;
        split4(v, h, l);
        *(uint2*)(g_W_h + mat*DD*DD + off*4) = h;
        *(uint2*)(g_W_l + mat*DD*DD + off*4) = l;
    }
}

// ---------------- cp.async double-buffered bf16-split GEMM ------------------
// C[(mat,)8192,256] = act(A @ W[mat] + bias + epvec);  A,W pre-split hi/lo.
// grid (4*nmat, 64); block tile 128x64, 8 warps 4Mx2N (warp tile 32x32), K-step 32.
#define A_STR 40
#define B_STR 72
#define ASZ (128*A_STR)    // 5120
#define WSZ (32*B_STR)     // 2304
#define GEMM_SMEM ((2*ASZ*2 + 2*WSZ*2) * 2)   // 59392 bytes
template<bool GO, bool HB, bool HE, bool SPLIT>
__global__ void __launch_bounds__(256, 2) gemm2_k(
    const bf16* __restrict__ Ah, const bf16* __restrict__ Al,
    const bf16* __restrict__ Wh, const bf16* __restrict__ Wl,
    bf16* __restrict__ Ch, bf16* __restrict__ Cl, float* __restrict__ Cf,
    const float* __restrict__ bias, const float* __restrict__ epvec)
{
    extern __shared__ char sm[];
    bf16* sAh = (bf16*)sm;
    bf16* sAl = sAh + 2*ASZ;
    bf16* sWh = sAl + 2*ASZ;
    bf16* sWl = sWh + 2*WSZ;

    const int tid  = threadIdx.x;
    const int warp = tid >> 5, lane = tid & 31;
    const int wm = warp & 3, wn = warp >> 2;
    const int mat  = blockIdx.x >> 2;
    const int col0 = (blockIdx.x & 3) * 64;
    const int row0 = blockIdx.y * 128;
    Wh += (size_t)mat * DD * DD;
    Wl += (size_t)mat * DD * DD;
    const size_t cofs = (size_t)mat * MTOT * DD;

    float acc[2][4][4];
    #pragma unroll
    for (int i = 0; i < 2; i++)
        #pragma unroll
        for (int j = 0; j < 4; j++)
            #pragma unroll
            for (int r = 0; r < 4; r++) acc[i][j][r] = 0.f;

    const int a_r_off = lane & 15;
    const int a_c_off = (lane >> 4) << 3;
    const int b_k_off = lane & 15;

    auto stage = [&](int kt, int bb) {
        // A: 128 rows x 32 cols -> 512 16B chunks
        #pragma unroll
        for (int c = tid; c < 512; c += 256) {
            const int ar = c >> 2, ac = (c & 3) * 8;
            const size_t ao = (size_t)(row0 + ar) * DD + kt*32 + ac;
            cp16(sAh + bb*ASZ + ar*A_STR + ac, Ah + ao);
            cp16(sAl + bb*ASZ + ar*A_STR + ac, Al + ao);
        }
        // W: 32 k-rows x 64 cols -> 256 16B chunks (one per thread)
        {
            const int wk = tid >> 3, wc = (tid & 7) * 8;
            const size_t wo = (size_t)(kt*32 + wk) * DD + col0 + wc;
            cp16(sWh + bb*WSZ + wk*B_STR + wc, Wh + wo);
            cp16(sWl + bb*WSZ + wk*B_STR + wc, Wl + wo);
        }
    };

    stage(0, 0);
    cp_commit();

    for (int kt = 0; kt < 8; kt++) {
        const int bb = kt & 1;
        cp_wait<0>();
        __syncthreads();
        if (kt < 7) { stage(kt + 1, bb ^ 1); cp_commit(); }

        #pragma unroll
        for (int kk = 0; kk < 32; kk += 16) {
            uint32_t ah[2][4], al[2][4];
            #pragma unroll
            for (int i = 0; i < 2; i++) {
                const int r = wm*32 + i*16 + a_r_off;
                const int c = kk + a_c_off;
                ldsm_x4(ah[i], smem_u32(sAh + bb*ASZ + r*A_STR + c));
                ldsm_x4(al[i], smem_u32(sAl + bb*ASZ + r*A_STR + c));
            }
            #pragma unroll
            for (int j = 0; j < 4; j++) {
                const int n  = wn*32 + j*8;
                const int kr = kk + b_k_off;
                uint32_t bh[2], bl[2];
                ldsm_x2t(bh, smem_u32(sWh + bb*WSZ + kr*B_STR + n));
                ldsm_x2t(bl, smem_u32(sWl + bb*WSZ + kr*B_STR + n));
                #pragma unroll
                for (int i = 0; i < 2; i++) {
                    mma16816(acc[i][j], ah[i], bh);
                    mma16816(acc[i][j], ah[i], bl);
                    mma16816(acc[i][j], al[i], bh);
                }
            }
        }
    }

    // ---- epilogue ----
    const int b = row0 >> 9;
    #pragma unroll
    for (int i = 0; i < 2; i++) {
        #pragma unroll
        for (int j = 0; j < 4; j++) {
            const int rbase = row0 + wm*32 + i*16 + (lane >> 2);
            const int cbase = col0 + wn*32 + j*8 + ((lane & 3) << 1);
            float2 v0 = make_float2(acc[i][j][0], acc[i][j][1]);
            float2 v1 = make_float2(acc[i][j][2], acc[i][j][3]);
            if (HB) {
                float2 bv = *(const float2*)(bias + cbase);
                v0.x += bv.x; v0.y += bv.y; v1.x += bv.x; v1.y += bv.y;
            }
            if (HE) {
                float2 ev = *(const float2*)(epvec + b * DD + cbase);
                v0.x += ev.x; v0.y += ev.y; v1.x += ev.x; v1.y += ev.y;
            }
            if (GO) {
                v0.x = gelu_f(v0.x); v0.y = gelu_f(v0.y);
                v1.x = gelu_f(v1.x); v1.y = gelu_f(v1.y);
            }
            const size_t o0 = cofs + (size_t)rbase * DD + cbase;
            const size_t o1 = cofs + (size_t)(rbase + 8) * DD + cbase;
            if (SPLIT) {
                uint32_t hw, lw;
                split_pack(v0.x, v0.y, hw, lw);
                *(uint32_t*)(Ch + o0) = hw;  *(uint32_t*)(Cl + o0) = lw;
                split_pack(v1.x, v1.y, hw, lw);
                *(uint32_t*)(Ch + o1) = hw;  *(uint32_t*)(Cl + o1) = lw;
            } else {
                *(float2*)(Cf + o0) = v0;
                *(float2*)(Cf + o1) = v1;
            }
        }
    }
}

// ---------------- tensor-core flash attention (pre-split inputs) ------------
#define QS 40
#define ATILE (128*QS)                 // 5120 elems / 10240 B
#define ATTN_SMEM (10*ATILE*2 + 896*4) // 105984 B (stats: 3*128 + 2*256 floats)
__global__ void __launch_bounds__(256, 1) attn2_k(
    const bf16* __restrict__ QKVh, const bf16* __restrict__ QKVl,
    bf16* __restrict__ Oh, bf16* __restrict__ Ol)
{
    extern __shared__ char smraw[];
    bf16* sQh = (bf16*)smraw;
    bf16* sQl = sQh + ATILE;
    bf16* sKV = sQl + ATILE;           // [buf][Kh,Kl,Vh,Vl] tiles
    float* m_run = (float*)(smraw + 10*ATILE*2);
    float* l_run = m_run + 128;
    float* alpha = l_run + 128;
    float* cmax  = alpha + 128;   // [2][128]
    float* psum  = cmax + 256;    // [2][128]

    const int tid  = threadIdx.x;
    const int warp = tid >> 5, lane = tid & 31;
    const int wm = warp & 3, wn = warp >> 2;
    const int lr = lane >> 2, lc = lane & 3;
    const int b = blockIdx.z, h = blockIdx.y;
    const int q0 = blockIdx.x * 128;
    const size_t KOFF = (size_t)MTOT * DD;
    const size_t VOFF = 2 * KOFF;

    // ---- stage Q ----
    {
        const size_t base = (size_t)(b*NN + q0) * DD + h * DKK;
        #pragma unroll
        for (int c = tid; c < 512; c += 256) {
            const int r = c >> 2, cc = (c & 3) * 8;
            const size_t so = base + (size_t)r * DD + cc;
            cp16(sQh + r*QS + cc, QKVh + so);
            cp16(sQl + r*QS + cc, QKVl + so);
        }
    }
    // ---- stage KV chunk ----
    auto stageKV = [&](int kc, int bufb) {
        const size_t base = (size_t)(b*NN + kc*128) * DD + h * DKK;
        bf16* dKh = sKV + bufb*4*ATILE;
        bf16* dKl = dKh + ATILE;
        bf16* dVh = dKl + ATILE;
        bf16* dVl = dVh + ATILE;
        #pragma unroll
        for (int c = tid; c < 512; c += 256) {
            const int r = c >> 2, cc = (c & 3) * 8;
            const size_t so = base + (size_t)r * DD + cc;
            cp16(dKh + r*QS + cc, QKVh + KOFF + so);
            cp16(dKl + r*QS + cc, QKVl + KOFF + so);
            cp16(dVh + r*QS + cc, QKVh + VOFF + so);
            cp16(dVl + r*QS + cc, QKVl + VOFF + so);
        }
    };
    stageKV(0, 0);
    cp_commit();

    if (tid < 128) { m_run[tid] = -1e30f; l_run[tid] = 0.f; }
    cp_wait<0>();
    __syncthreads();

    // ---- Q fragments in registers for whole kernel ----
    uint32_t qh[2][2][4], ql[2][2][4];
    #pragma unroll
    for (int i = 0; i < 2; i++)
        #pragma unroll
        for (int ks = 0; ks < 2; ks++) {
            const int r = wm*32 + i*16 + (lane & 15);
            const int c = ks*16 + ((lane >> 4) << 3);
            ldsm_x4(qh[i][ks], smem_u32(sQh + r*QS + c));
            ldsm_x4(ql[i][ks], smem_u32(sQl + r*QS + c));
        }

    float ofrag[2][4][4];
    #pragma unroll
    for (int i = 0; i < 2; i++)
        #pragma unroll
        for (int n = 0; n < 4; n++)
            #pragma unroll
            for (int r = 0; r < 4; r++) ofrag[i][n][r] = 0.f;

    for (int kc = 0; kc < 4; kc++) {
        const int bb = kc & 1;
        if (kc > 0) { cp_wait<0>(); }
        __syncthreads();
        if (kc < 3) { stageKV(kc + 1, bb ^ 1); cp_commit(); }

        bf16* Khb = sKV + bb*4*ATILE;
        bf16* Klb = Khb + ATILE;
        bf16* Vhb = Klb + ATILE;
        bf16* Vlb = Vhb + ATILE;

        // ---- S = Q K^T ----
        float sfr[2][8][4];
        #pragma unroll
        for (int i = 0; i < 2; i++)
            #pragma unroll
            for (int j = 0; j < 8; j++)
                #pragma unroll
                for (int r = 0; r < 4; r++) sfr[i][j][r] = 0.f;

        #pragma unroll
        for (int j = 0; j < 8; j++) {
            const int krow = wn*64 + j*8 + (lane & 7);
            uint32_t bh[2][2], bl[2][2];
            #pragma unroll
            for (int ks = 0; ks < 2; ks++) {
                const int kcol = ks*16 + (((lane >> 3) & 1) << 3);
                ldsm_x2(bh[ks], smem_u32(Khb + krow*QS + kcol));
                ldsm_x2(bl[ks], smem_u32(Klb + krow*QS + kcol));
            }
            #pragma unroll
            for (int i = 0; i < 2; i++)
                #pragma unroll
                for (int ks = 0; ks < 2; ks++) {
                    mma16816(sfr[i][j], qh[i][ks], bh[ks]);
                    mma16816(sfr[i][j], qh[i][ks], bl[ks]);
                    mma16816(sfr[i][j], ql[i][ks], bh[ks]);
                }
        }
        // scale S by 1/sqrt(DK) (exact, post-mma)
        const float sc = 0.17677669529663689f;
        #pragma unroll
        for (int i = 0; i < 2; i++)
            #pragma unroll
            for (int j = 0; j < 8; j++) {
                sfr[i][j][0] *= sc; sfr[i][j][1] *= sc;
                sfr[i][j][2] *= sc; sfr[i][j][3] *= sc;
            }

        // ---- per-row chunk max ----
        float tmax[2][2];
        #pragma unroll
        for (int i = 0; i < 2; i++) {
            tmax[i][0] = -1e30f; tmax[i][1] = -1e30f;
            #pragma unroll
            for (int j = 0; j < 8; j++) {
                tmax[i][0] = fmaxf(tmax[i][0], fmaxf(sfr[i][j][0], sfr[i][j][1]));
                tmax[i][1] = fmaxf(tmax[i][1], fmaxf(sfr[i][j][2], sfr[i][j][3]));
            }
            #pragma unroll
            for (int off = 1; off <= 2; off <<= 1) {
                tmax[i][0] = fmaxf(tmax[i][0], __shfl_xor_sync(0xffffffffu, tmax[i][0], off));
                tmax[i][1] = fmaxf(tmax[i][1], __shfl_xor_sync(0xffffffffu, tmax[i][1], off));
            }
        }
        if (lc == 0) {
            #pragma unroll
            for (int i = 0; i < 2; i++) {
                cmax[wn*128 + wm*32 + i*16 + lr]     = tmax[i][0];
                cmax[wn*128 + wm*32 + i*16 + lr + 8] = tmax[i][1];
            }
        }
        __syncthreads();

        if (warp < 4) {
            const int r = wm*32 + lane;
            float cm = fmaxf(cmax[r], cmax[128 + r]);
            float mo = m_run[r];
            float mn = fmaxf(mo, cm);
            float a  = __expf(mo - mn);
            m_run[r] = mn;
            l_run[r] *= a;
            alpha[r] = a;
        }
        __syncthreads();

        // ---- exp, psum, rescale O ----
        float mrow[2][2], arow[2][2];
        #pragma unroll
        for (int i = 0; i < 2; i++) {
            mrow[i][0] = m_run[wm*32 + i*16 + lr];
            mrow[i][1] = m_run[wm*32 + i*16 + lr + 8];
            arow[i][0] = alpha[wm*32 + i*16 + lr];
            arow[i][1] = alpha[wm*32 + i*16 + lr + 8];
        }
        float ps[2][2] = {{0.f,0.f},{0.f,0.f}};
        #pragma unroll
        for (int i = 0; i < 2; i++)
            #pragma unroll
            for (int j = 0; j < 8; j++) {
                sfr[i][j][0] = __expf(sfr[i][j][0] - mrow[i][0]);
                sfr[i][j][1] = __expf(sfr[i][j][1] - mrow[i][0]);
                sfr[i][j][2] = __expf(sfr[i][j][2] - mrow[i][1]);
                sfr[i][j][3] = __expf(sfr[i][j][3] - mrow[i][1]);
                ps[i][0] += sfr[i][j][0] + sfr[i][j][1];
                ps[i][1] += sfr[i][j][2] + sfr[i][j][3];
            }
        #pragma unroll
        for (int i = 0; i < 2; i++)
            #pragma unroll
            for (int off = 1; off <= 2; off <<= 1) {
                ps[i][0] += __shfl_xor_sync(0xffffffffu, ps[i][0], off);
                ps[i][1] += __shfl_xor_sync(0xffffffffu, ps[i][1], off);
            }
        if (lc == 0) {
            #pragma unroll
            for (int i = 0; i < 2; i++) {
                psum[wn*128 + wm*32 + i*16 + lr]     = ps[i][0];
                psum[wn*128 + wm*32 + i*16 + lr + 8] = ps[i][1];
            }
        }
        #pragma unroll
        for (int i = 0; i < 2; i++)
            #pragma unroll
            for (int n = 0; n < 4; n++) {
                ofrag[i][n][0] *= arow[i][0];
                ofrag[i][n][1] *= arow[i][0];
                ofrag[i][n][2] *= arow[i][1];
                ofrag[i][n][3] *= arow[i][1];
            }

        // ---- O += P V ----
        #pragma unroll
        for (int ks = 0; ks < 4; ks++) {
            uint32_t ah[2][4], al[2][4];
            #pragma unroll
            for (int i = 0; i < 2; i++) {
                const int j0 = 2*ks, j1 = 2*ks + 1;
                split_pack(sfr[i][j0][0], sfr[i][j0][1], ah[i][0], al[i][0]);
                split_pack(sfr[i][j0][2], sfr[i][j0][3], ah[i][1], al[i][1]);
                split_pack(sfr[i][j1][0], sfr[i][j1][1], ah[i][2], al[i][2]);
                split_pack(sfr[i][j1][2], sfr[i][j1][3], ah[i][3], al[i][3]);
            }
            const int vrow = wn*64 + ks*16 + (lane & 7) + (((lane >> 3) & 1) << 3);
            #pragma unroll
            for (int nb = 0; nb < 4; nb++) {
                uint32_t bvh[2], bvl[2];
                ldsm_x2t(bvh, smem_u32(Vhb + vrow*QS + nb*8));
                ldsm_x2t(bvl, smem_u32(Vlb + vrow*QS + nb*8));
                #pragma unroll
                for (int i = 0; i < 2; i++) {
                    mma16816(ofrag[i][nb], ah[i], bvh);
                    mma16816(ofrag[i][nb], ah[i], bvl);
                    mma16816(ofrag[i][nb], al[i], bvh);
                }
            }
        }
        __syncthreads();
        if (warp < 4) {
            const int r = wm*32 + lane;
            l_run[r] += psum[r] + psum[128 + r];
        }
        __syncthreads();
    }

    // ---- combine wn halves, normalize, split-store ----
    float* Osm = (float*)smraw;   // 16KB overlay on Q region (Q no longer needed)
    if (wn == 1) {
        #pragma unroll
        for (int i = 0; i < 2; i++)
            #pragma unroll
            for (int nb = 0; nb < 4; nb++) {
                const int rt = i*16 + lr;
                const int d  = nb*8 + lc*2;
                Osm[wm*1024 + rt*32 + d]       = ofrag[i][nb][0];
                Osm[wm*1024 + rt*32 + d + 1]   = ofrag[i][nb][1];
                Osm[wm*1024 + (rt+8)*32 + d]   = ofrag[i][nb][2];
                Osm[wm*1024 + (rt+8)*32 + d+1] = ofrag[i][nb][3];
            }
    }
    __syncthreads();
    if (wn == 0) {
        #pragma unroll
        for (int i = 0; i < 2; i++) {
            const int rt0 = i*16 + lr;
            const float li0 = 1.f / l_run[wm*32 + rt0];
            const float li1 = 1.f / l_run[wm*32 + rt0 + 8];
            #pragma unroll
            for (int nb = 0; nb < 4; nb++) {
                const int d = nb*8 + lc*2;
                float2 v0 = make_float2(
                    (ofrag[i][nb][0] + Osm[wm*1024 + rt0*32 + d])     * li0,
                    (ofrag[i][nb][1] + Osm[wm*1024 + rt0*32 + d + 1]) * li0);
                float2 v1 = make_float2(
                    (ofrag[i][nb][2] + Osm[wm*1024 + (rt0+8)*32 + d])     * li1,
                    (ofrag[i][nb][3] + Osm[wm*1024 + (rt0+8)*32 + d + 1]) * li1);
                const size_t rg = (size_t)(b*NN + q0 + wm*32 + rt0);
                uint32_t hw, lw;
                split_pack(v0.x, v0.y, hw, lw);
                *(uint32_t*)(Oh + rg*DD + h*DKK + d) = hw;
                *(uint32_t*)(Ol + rg*DD + h*DKK + d) = lw;
                split_pack(v1.x, v1.y, hw, lw);
                *(uint32_t*)(Oh + (rg+8)*DD + h*DKK + d) = hw;
                *(uint32_t*)(Ol + (rg+8)*DD + h*DKK + d) = lw;
            }
        }
    }
}

// ---------------- aggregation ------------------------------------------------
__global__ void __launch_bounds__(256) aggr_k(
    const float* __restrict__ X2, const float* __restrict__ res_W,
    const float* __restrict__ res_b, const float* __restrict__ ff_W1,
    float* __restrict__ topvec)
{
    __shared__ float g[DD];
    __shared__ float ga[DD];
    const int b = blockIdx.x, t = threadIdx.x;

    float s = 0.f;
    const float* xb = X2 + (size_t)(b*NN) * DD + t;
    for (int n = 0; n < NN; n++) s += xb[(size_t)n * DD];
    g[t] = gelu_f(s * (1.0f / NN));
    __syncthreads();

    float a = res_b[t];
    for (int i = 0; i < DD; i++) a += g[i] * res_W[(size_t)i * DD + t];
    ga[t] = gelu_f(a);
    __syncthreads();

    float tv = 0.f;
    for (int i = 0; i < DD; i++) tv += ga[i] * ff_W1[(size_t)i * DD + t];
    topvec[b * DD + t] = tv;
}

// ---------------- prototypes ------------------------------------------------
__global__ void __launch_bounds__(256) proto_k(
    const float* __restrict__ F, const int* __restrict__ labels,
    float* __restrict__ P, float* __restrict__ counts)
{
    __shared__ float Ps[CC*DD];
    __shared__ int   labs[NN];
    const int b = blockIdx.x, t = threadIdx.x;

    for (int i = t; i < CC*DD; i += 256) Ps[i] = 0.f;
    for (int i = t; i < NN; i += 256) labs[i] = labels[b*NN + i];
    __syncthreads();

    const float* fb = F + (size_t)(b*NN) * DD + t;
    for (int n = 0; n < NN; n++)
        Ps[labs[n]*DD + t] += fb[(size_t)n * DD];
    __syncthreads();

    for (int i = t; i < CC*DD; i += 256) P[(size_t)b*CC*DD + i] = Ps[i];
    if (t < CC) {
        int cnt = 0;
        for (int n = 0; n < NN; n++) cnt += (labs[n] == t);
        counts[b*CC + t] = (float)cnt;
    }
}

// ---------------- scoring ---------------------------------------------------
__global__ void __launch_bounds__(256) score_k(
    const float* __restrict__ F, const float* __restrict__ P,
    const float* __restrict__ counts, const int* __restrict__ labels,
    float* __restrict__ out)
{
    __shared__ float Ps[CC*DD];
    __shared__ float cs[CC];
    const int b = blockIdx.y;
    for (int i = threadIdx.x; i < CC*DD; i += 256) Ps[i] = P[(size_t)b*CC*DD + i];
    if (threadIdx.x < CC) cs[threadIdx.x] = counts[b*CC + threadIdx.x];
    __syncthreads();

    const int warp = threadIdx.x >> 5, lane = threadIdx.x & 31;
    const int n = blockIdx.x * 8 + warp;
    const float* f = F + (size_t)(b*NN + n) * DD;

    float dot[CC];
    #pragma unroll
    for (int c = 0; c < CC; c++) dot[c] = 0.f;
    float nrm = 0.f;

    for (int d = lane; d < DD; d += 32) {
        float fv = f[d];
        nrm += fv * fv;
        #pragma unroll
        for (int c = 0; c < CC; c++) dot[c] += fv * Ps[c*DD + d];
    }
    #pragma unroll
    for (int off = 16; off > 0; off >>= 1) {
        nrm += __shfl_xor_sync(0xffffffffu, nrm, off);
        #pragma unroll
        for (int c = 0; c < CC; c++)
            dot[c] += __shfl_xor_sync(0xffffffffu, dot[c], off);
    }
    if (lane < CC) {
        const int c = lane;
        const int lab = labels[b*NN + n];
        const float mm = (lab == c) ? 1.f : 0.f;
        out[(size_t)(b*NN + n) * CC + c] = (dot[c] - mm * nrm) / (cs[c] - mm);
    }
}

// ---------------- launcher -------------------------------------------------
extern "C" void kernel_launch(void* const* d_in, const int* in_sizes, int n_in,
                              void* d_out, int out_size)
{
    const float* emb    = (const float*)d_in[0];
    const int*   labels = (const int*)  d_in[1];
    const float* Wq0 = (const float*)d_in[2];
    const float* Wk0 = (const float*)d_in[3];
    const float* Wv0 = (const float*)d_in[4];
    const float* Wo0 = (const float*)d_in[5];
    const float* Wq1 = (const float*)d_in[6];
    const float* Wk1 = (const float*)d_in[7];
    const float* Wv1 = (const float*)d_in[8];
    const float* Wo1 = (const float*)d_in[9];
    const float* res_W = (const float*)d_in[10];
    const float* res_b = (const float*)d_in[11];
    const float* ff_W1 = (const float*)d_in[12];
    const float* ff_b1 = (const float*)d_in[13];
    const float* ff_W2 = (const float*)d_in[14];
    const float* ff_b2 = (const float*)d_in[15];
    float* out = (float*)d_out;

    bf16 *emb_h, *emb_l, *gemb_h, *gemb_l, *W_h, *W_l, *QKV_h, *QKV_l;
    bf16 *pA_h, *pA_l, *pB_h, *pB_l;
    float *X32, *tv, *P, *cnt;
    cudaGetSymbolAddress((void**)&emb_h,  g_emb_h);
    cudaGetSymbolAddress((void**)&emb_l,  g_emb_l);
    cudaGetSymbolAddress((void**)&gemb_h, g_gemb_h);
    cudaGetSymbolAddress((void**)&gemb_l, g_gemb_l);
    cudaGetSymbolAddress((void**)&W_h,    g_W_h);
    cudaGetSymbolAddress((void**)&W_l,    g_W_l);
    cudaGetSymbolAddress((void**)&QKV_h,  g_QKV_h);
    cudaGetSymbolAddress((void**)&QKV_l,  g_QKV_l);
    cudaGetSymbolAddress((void**)&pA_h,   g_pA_h);
    cudaGetSymbolAddress((void**)&pA_l,   g_pA_l);
    cudaGetSymbolAddress((void**)&pB_h,   g_pB_h);
    cudaGetSymbolAddress((void**)&pB_l,   g_pB_l);
    cudaGetSymbolAddress((void**)&X32,    g_X32);
    cudaGetSymbolAddress((void**)&tv,     g_topvec);
    cudaGetSymbolAddress((void**)&P,      g_P);
    cudaGetSymbolAddress((void**)&cnt,    g_counts);

    cudaFuncSetAttribute(gemm2_k<false,false,false,true >, cudaFuncAttributeMaxDynamicSharedMemorySize, GEMM_SMEM);
    cudaFuncSetAttribute(gemm2_k<true ,false,false,true >, cudaFuncAttributeMaxDynamicSharedMemorySize, GEMM_SMEM);
    cudaFuncSetAttribute(gemm2_k<false,false,false,false>, cudaFuncAttributeMaxDynamicSharedMemorySize, GEMM_SMEM);
    cudaFuncSetAttribute(gemm2_k<true ,true ,true ,true >, cudaFuncAttributeMaxDynamicSharedMemorySize, GEMM_SMEM);
    cudaFuncSetAttribute(gemm2_k<false,true ,false,false>, cudaFuncAttributeMaxDynamicSharedMemorySize, GEMM_SMEM);
    cudaFuncSetAttribute(attn2_k, cudaFuncAttributeMaxDynamicSharedMemorySize, ATTN_SMEM);

    const dim3 g3(12, 64);   // fused QKV (3 mats x 4 col-tiles)
    const dim3 g1(4, 64);    // single GEMM (4 col-tiles)
    const dim3 ag(NN/128, HH, BB);

    // ---- prep: split emb/gelu(emb)/weights ----
    prep_k<<<2688, 256>>>(emb, Wq0, Wk0, Wv0, Wo0, Wq1, Wk1, Wv1, Wo1, ff_W1, ff_W2);

    // ---- MHA 0 ----
    gemm2_k<false,false,false,true ><<<g3, 256, GEMM_SMEM>>>(emb_h, emb_l, W_h, W_l, QKV_h, QKV_l, nullptr, nullptr, nullptr);
    attn2_k<<<ag, 256, ATTN_SMEM>>>(QKV_h, QKV_l, pA_h, pA_l);
    gemm2_k<true ,false,false,true ><<<g1, 256, GEMM_SMEM>>>(pA_h, pA_l, W_h + 3*DD*DD, W_l + 3*DD*DD, pB_h, pB_l, nullptr, nullptr, nullptr);

    // ---- MHA 1 ----
    gemm2_k<false,false,false,true ><<<g3, 256, GEMM_SMEM>>>(pB_h, pB_l, W_h + 4*DD*DD, W_l + 4*DD*DD, QKV_h, QKV_l, nullptr, nullptr, nullptr);
    attn2_k<<<ag, 256, ATTN_SMEM>>>(QKV_h, QKV_l, pA_h, pA_l);
    gemm2_k<false,false,false,false><<<g1, 256, GEMM_SMEM>>>(pA_h, pA_l, W_h + 7*DD*DD, W_l + 7*DD*DD, nullptr, nullptr, X32, nullptr, nullptr);

    // ---- aggregation ----
    aggr_k<<<BB, 256>>>(X32, res_W, res_b, ff_W1, tv);

    // ---- FF ----
    gemm2_k<true ,true ,true ,true ><<<g1, 256, GEMM_SMEM>>>(gemb_h, gemb_l, W_h + 8*DD*DD, W_l + 8*DD*DD, pB_h, pB_l, nullptr, ff_b1, tv);
    gemm2_k<false,true ,false,false><<<g1, 256, GEMM_SMEM>>>(pB_h, pB_l, W_h + 9*DD*DD, W_l + 9*DD*DD, nullptr, nullptr, X32, ff_b2, nullptr);

    // ---- prototypes + scoring ----
    proto_k<<<BB, 256>>>(X32, labels, P, cnt);
    score_k<<<dim3(NN/8, BB), 256>>>(X32, P, cnt, labels, out);
}

// round 14
// speedup vs baseline: 1.0264x; 1.0264x over previous
#include <cuda_runtime.h>
#include <cuda_bf16.h>
#include <math.h>
#include <stdint.h>

#define BB   16
#define NN   512
#define DD   256
#define HH   8
#define DKK  32
#define CC   16
#define MTOT (BB*NN)   // 8192
typedef __nv_bfloat16 bf16;

// ---------------- scratch (device globals: no allocation allowed) ----------
__device__ __align__(16) bf16 g_emb_h[MTOT*DD],  g_emb_l[MTOT*DD];
__device__ __align__(16) bf16 g_gemb_h[MTOT*DD], g_gemb_l[MTOT*DD];
__device__ __align__(16) bf16 g_W_h[10*DD*DD],   g_W_l[10*DD*DD];
__device__ __align__(16) bf16 g_QKV_h[3*MTOT*DD], g_QKV_l[3*MTOT*DD];
__device__ __align__(16) bf16 g_pA_h[MTOT*DD],  g_pA_l[MTOT*DD];
__device__ __align__(16) bf16 g_pB_h[MTOT*DD],  g_pB_l[MTOT*DD];
__device__ float g_X32[MTOT*DD];
__device__ float g_topvec[BB*DD];
__device__ float g_P[BB*CC*DD];
__device__ float g_counts[BB*CC];

__device__ __forceinline__ float gelu_f(float x) {
    return 0.5f * x * (1.0f + erff(x * 0.7071067811865475f));
}

// ---------------- helpers ----------------------------------------------
__device__ __forceinline__ uint32_t smem_u32(const void* p) {
    return (uint32_t)__cvta_generic_to_shared(p);
}
__device__ __forceinline__ void cp16(void* dst, const void* src) {
    asm volatile("cp.async.cg.shared.global [%0], [%1], 16;"
                 :: "r"(smem_u32(dst)), "l"(src));
}
__device__ __forceinline__ void cp_commit() { asm volatile("cp.async.commit_group;"); }
template<int N> __device__ __forceinline__ void cp_wait() {
    asm volatile("cp.async.wait_group %0;" :: "n"(N));
}
__device__ __forceinline__ void ldsm_x4(uint32_t* r, uint32_t addr) {
    asm volatile("ldmatrix.sync.aligned.m8n8.x4.shared.b16 {%0,%1,%2,%3}, [%4];"
                 : "=r"(r[0]), "=r"(r[1]), "=r"(r[2]), "=r"(r[3]) : "r"(addr));
}
__device__ __forceinline__ void ldsm_x2(uint32_t* r, uint32_t addr) {
    asm volatile("ldmatrix.sync.aligned.m8n8.x2.shared.b16 {%0,%1}, [%2];"
                 : "=r"(r[0]), "=r"(r[1]) : "r"(addr));
}
__device__ __forceinline__ void ldsm_x2t(uint32_t* r, uint32_t addr) {
    asm volatile("ldmatrix.sync.aligned.m8n8.x2.trans.shared.b16 {%0,%1}, [%2];"
                 : "=r"(r[0]), "=r"(r[1]) : "r"(addr));
}
__device__ __forceinline__ void mma16816(float* d, const uint32_t* a, const uint32_t* b) {
    asm volatile(
        "mma.sync.aligned.m16n8k16.row.col.f32.bf16.bf16.f32 "
        "{%0,%1,%2,%3}, {%4,%5,%6,%7}, {%8,%9}, {%0,%1,%2,%3};"
        : "+f"(d[0]), "+f"(d[1]), "+f"(d[2]), "+f"(d[3])
        : "r"(a[0]), "r"(a[1]), "r"(a[2]), "r"(a[3]), "r"(b[0]), "r"(b[1]));
}
__device__ __forceinline__ void split_pack(float x, float y, uint32_t& hi, uint32_t& lo) {
    __nv_bfloat16 hx = __float2bfloat16(x);
    __nv_bfloat16 hy = __float2bfloat16(y);
    __nv_bfloat16 lx = __float2bfloat16(x - __bfloat162float(hx));
    __nv_bfloat16 ly = __float2bfloat16(y - __bfloat162float(hy));
    __nv_bfloat162 H(hx, hy), L(lx, ly);
    hi = *(uint32_t*)&H;
    lo = *(uint32_t*)&L;
}
__device__ __forceinline__ void split4(float4 v, uint2& h, uint2& l) {
    uint32_t h0, l0, h1, l1;
    split_pack(v.x, v.y, h0, l0);
    split_pack(v.z, v.w, h1, l1);
    h = make_uint2(h0, h1);
    l = make_uint2(l0, l1);
}

// ---------------- prep: split emb, gelu(emb), and 10 weights once ----------
#define EMB_QUADS (MTOT*DD/4)      // 524288
__global__ void __launch_bounds__(256) prep_k(
    const float* __restrict__ emb,
    const float* __restrict__ Wq0, const float* __restrict__ Wk0,
    const float* __restrict__ Wv0, const float* __restrict__ Wo0,
    const float* __restrict__ Wq1, const float* __restrict__ Wk1,
    const float* __restrict__ Wv1, const float* __restrict__ Wo1,
    const float* __restrict__ ffW1, const float* __restrict__ ffW2)
{
    int idx = blockIdx.x * 256 + threadIdx.x;
    if (idx < EMB_QUADS) {
        float4 v = ((const float4*)emb)[idx];
        uint2 h, l;
        split4(v, h, l);
        *(uint2*)(g_emb_h + idx*4) = h;
        *(uint2*)(g_emb_l + idx*4) = l;
        v.x = gelu_f(v.x); v.y = gelu_f(v.y); v.z = gelu_f(v.z); v.w = gelu_f(v.w);
        split4(v, h, l);
        *(uint2*)(g_gemb_h + idx*4) = h;
        *(uint2*)(g_gemb_l + idx*4) = l;
    } else {
        int w = idx - EMB_QUADS;
        int mat = w >> 14;          // 16384 quads per 256x256 matrix
        int off = w & 16383;
        const float* src;
        switch (mat) {
            case 0: src = Wq0; break;  case 1: src = Wk0; break;
            case 2: src = Wv0; break;  case 3: src = Wo0; break;
            case 4: src = Wq1; break;  case 5: src = Wk1; break;
            case 6: src = Wv1; break;  case 7: src = Wo1; break;
            case 8: src = ffW1 + DD*DD; break;   // bottom half of ff_W1
            default: src = ffW2; break;
        }
        float4 v = ((const float4*)src)[off];
        uint2 h, l;
        split4(v, h, l);
        *(uint2*)(g_W_h + mat*DD*DD + off*4) = h;
        *(uint2*)(g_W_l + mat*DD*DD + off*4) = l;
    }
}

// ---------------- cp.async double-buffered bf16-split GEMM ------------------
// C[(mat,)8192,256] = act(A @ W[mat] + bias + epvec);  A,W pre-split hi/lo.
// Block tile 128 x BN, 8 warps 4M x 2N, K-step 32. BN in {64,128}.
#define A_STR 40
#define ASZ (128*A_STR)    // 5120 elems
template<int BN>
struct GCfg {
    static constexpr int B_STR = BN + 8;
    static constexpr int WSZ   = 32 * B_STR;
    static constexpr int NJ    = BN / 16;           // j-blocks per warp
    static constexpr int SMEM  = (2*ASZ*2 + 2*WSZ*2) * 2;  // bytes
    static constexpr int NCT   = DD / BN;           // col tiles per matrix
};
template<int BN, bool GO, bool HB, bool HE, bool SPLIT>
__global__ void __launch_bounds__(256, 2) gemm2_k(
    const bf16* __restrict__ Ah, const bf16* __restrict__ Al,
    const bf16* __restrict__ Wh, const bf16* __restrict__ Wl,
    bf16* __restrict__ Ch, bf16* __restrict__ Cl, float* __restrict__ Cf,
    const float* __restrict__ bias, const float* __restrict__ epvec)
{
    constexpr int B_STR = GCfg<BN>::B_STR;
    constexpr int WSZ   = GCfg<BN>::WSZ;
    constexpr int NJ    = GCfg<BN>::NJ;
    constexpr int NCT   = GCfg<BN>::NCT;

    extern __shared__ char sm[];
    bf16* sAh = (bf16*)sm;
    bf16* sAl = sAh + 2*ASZ;
    bf16* sWh = sAl + 2*ASZ;
    bf16* sWl = sWh + 2*WSZ;

    const int tid  = threadIdx.x;
    const int warp = tid >> 5, lane = tid & 31;
    const int wm = warp & 3, wn = warp >> 2;
    const int mat  = blockIdx.x / NCT;
    const int col0 = (blockIdx.x % NCT) * BN;
    const int row0 = blockIdx.y * 128;
    Wh += (size_t)mat * DD * DD;
    Wl += (size_t)mat * DD * DD;
    const size_t cofs = (size_t)mat * MTOT * DD;

    float acc[2][NJ][4];
    #pragma unroll
    for (int i = 0; i < 2; i++)
        #pragma unroll
        for (int j = 0; j < NJ; j++)
            #pragma unroll
            for (int r = 0; r < 4; r++) acc[i][j][r] = 0.f;

    const int a_r_off = lane & 15;
    const int a_c_off = (lane >> 4) << 3;
    const int b_k_off = lane & 15;

    auto stage = [&](int kt, int bb) {
        // A: 128 rows x 32 cols -> 512 16B chunks
        #pragma unroll
        for (int c = tid; c < 512; c += 256) {
            const int ar = c >> 2, ac = (c & 3) * 8;
            const size_t ao = (size_t)(row0 + ar) * DD + kt*32 + ac;
            cp16(sAh + bb*ASZ + ar*A_STR + ac, Ah + ao);
            cp16(sAl + bb*ASZ + ar*A_STR + ac, Al + ao);
        }
        // W: 32 k-rows x BN cols -> BN*4 16B chunks
        #pragma unroll
        for (int c = tid; c < BN*4; c += 256) {
            const int wk = c / (BN/8), wc = (c % (BN/8)) * 8;
            const size_t wo = (size_t)(kt*32 + wk) * DD + col0 + wc;
            cp16(sWh + bb*WSZ + wk*B_STR + wc, Wh + wo);
            cp16(sWl + bb*WSZ + wk*B_STR + wc, Wl + wo);
        }
    };

    stage(0, 0);
    cp_commit();

    for (int kt = 0; kt < 8; kt++) {
        const int bb = kt & 1;
        cp_wait<0>();
        __syncthreads();
        if (kt < 7) { stage(kt + 1, bb ^ 1); cp_commit(); }

        #pragma unroll
        for (int kk = 0; kk < 32; kk += 16) {
            uint32_t ah[2][4], al[2][4];
            #pragma unroll
            for (int i = 0; i < 2; i++) {
                const int r = wm*32 + i*16 + a_r_off;
                const int c = kk + a_c_off;
                ldsm_x4(ah[i], smem_u32(sAh + bb*ASZ + r*A_STR + c));
                ldsm_x4(al[i], smem_u32(sAl + bb*ASZ + r*A_STR + c));
            }
            #pragma unroll
            for (int j = 0; j < NJ; j++) {
                const int n  = wn*(BN/2) + j*8;
                const int kr = kk + b_k_off;
                uint32_t bh[2], bl[2];
                ldsm_x2t(bh, smem_u32(sWh + bb*WSZ + kr*B_STR + n));
                ldsm_x2t(bl, smem_u32(sWl + bb*WSZ + kr*B_STR + n));
                #pragma unroll
                for (int i = 0; i < 2; i++) {
                    mma16816(acc[i][j], ah[i], bh);
                    mma16816(acc[i][j], ah[i], bl);
                    mma16816(acc[i][j], al[i], bh);
                }
            }
        }
    }

    // ---- epilogue ----
    const int b = row0 >> 9;
    #pragma unroll
    for (int i = 0; i < 2; i++) {
        #pragma unroll
        for (int j = 0; j < NJ; j++) {
            const int rbase = row0 + wm*32 + i*16 + (lane >> 2);
            const int cbase = col0 + wn*(BN/2) + j*8 + ((lane & 3) << 1);
            float2 v0 = make_float2(acc[i][j][0], acc[i][j][1]);
            float2 v1 = make_float2(acc[i][j][2], acc[i][j][3]);
            if (HB) {
                float2 bv = *(const float2*)(bias + cbase);
                v0.x += bv.x; v0.y += bv.y; v1.x += bv.x; v1.y += bv.y;
            }
            if (HE) {
                float2 ev = *(const float2*)(epvec + b * DD + cbase);
                v0.x += ev.x; v0.y += ev.y; v1.x += ev.x; v1.y += ev.y;
            }
            if (GO) {
                v0.x = gelu_f(v0.x); v0.y = gelu_f(v0.y);
                v1.x = gelu_f(v1.x); v1.y = gelu_f(v1.y);
            }
            const size_t o0 = cofs + (size_t)rbase * DD + cbase;
            const size_t o1 = cofs + (size_t)(rbase + 8) * DD + cbase;
            if (SPLIT) {
                uint32_t hw, lw;
                split_pack(v0.x, v0.y, hw, lw);
                *(uint32_t*)(Ch + o0) = hw;  *(uint32_t*)(Cl + o0) = lw;
                split_pack(v1.x, v1.y, hw, lw);
                *(uint32_t*)(Ch + o1) = hw;  *(uint32_t*)(Cl + o1) = lw;
            } else {
                *(float2*)(Cf + o0) = v0;
                *(float2*)(Cf + o1) = v1;
            }
        }
    }
}

// ---------------- tensor-core flash attention (pre-split inputs) ------------
#define QS 40
#define ATILE (128*QS)                 // 5120 elems / 10240 B
#define ATTN_SMEM (10*ATILE*2 + 896*4) // 105984 B (stats: 3*128 + 2*256 floats)
__global__ void __launch_bounds__(256, 1) attn2_k(
    const bf16* __restrict__ QKVh, const bf16* __restrict__ QKVl,
    bf16* __restrict__ Oh, bf16* __restrict__ Ol)
{
    extern __shared__ char smraw[];
    bf16* sQh = (bf16*)smraw;
    bf16* sQl = sQh + ATILE;
    bf16* sKV = sQl + ATILE;           // [buf][Kh,Kl,Vh,Vl] tiles
    float* m_run = (float*)(smraw + 10*ATILE*2);
    float* l_run = m_run + 128;
    float* alpha = l_run + 128;
    float* cmax  = alpha + 128;   // [2][128]
    float* psum  = cmax + 256;    // [2][128]

    const int tid  = threadIdx.x;
    const int warp = tid >> 5, lane = tid & 31;
    const int wm = warp & 3, wn = warp >> 2;
    const int lr = lane >> 2, lc = lane & 3;
    const int b = blockIdx.z, h = blockIdx.y;
    const int q0 = blockIdx.x * 128;
    const size_t KOFF = (size_t)MTOT * DD;
    const size_t VOFF = 2 * KOFF;

    // ---- stage Q ----
    {
        const size_t base = (size_t)(b*NN + q0) * DD + h * DKK;
        #pragma unroll
        for (int c = tid; c < 512; c += 256) {
            const int r = c >> 2, cc = (c & 3) * 8;
            const size_t so = base + (size_t)r * DD + cc;
            cp16(sQh + r*QS + cc, QKVh + so);
            cp16(sQl + r*QS + cc, QKVl + so);
        }
    }
    // ---- stage KV chunk ----
    auto stageKV = [&](int kc, int bufb) {
        const size_t base = (size_t)(b*NN + kc*128) * DD + h * DKK;
        bf16* dKh = sKV + bufb*4*ATILE;
        bf16* dKl = dKh + ATILE;
        bf16* dVh = dKl + ATILE;
        bf16* dVl = dVh + ATILE;
        #pragma unroll
        for (int c = tid; c < 512; c += 256) {
            const int r = c >> 2, cc = (c & 3) * 8;
            const size_t so = base + (size_t)r * DD + cc;
            cp16(dKh + r*QS + cc, QKVh + KOFF + so);
            cp16(dKl + r*QS + cc, QKVl + KOFF + so);
            cp16(dVh + r*QS + cc, QKVh + VOFF + so);
            cp16(dVl + r*QS + cc, QKVl + VOFF + so);
        }
    };
    stageKV(0, 0);
    cp_commit();

    if (tid < 128) { m_run[tid] = -1e30f; l_run[tid] = 0.f; }
    cp_wait<0>();
    __syncthreads();

    // ---- Q fragments in registers for whole kernel ----
    uint32_t qh[2][2][4], ql[2][2][4];
    #pragma unroll
    for (int i = 0; i < 2; i++)
        #pragma unroll
        for (int ks = 0; ks < 2; ks++) {
            const int r = wm*32 + i*16 + (lane & 15);
            const int c = ks*16 + ((lane >> 4) << 3);
            ldsm_x4(qh[i][ks], smem_u32(sQh + r*QS + c));
            ldsm_x4(ql[i][ks], smem_u32(sQl + r*QS + c));
        }

    float ofrag[2][4][4];
    #pragma unroll
    for (int i = 0; i < 2; i++)
        #pragma unroll
        for (int n = 0; n < 4; n++)
            #pragma unroll
            for (int r = 0; r < 4; r++) ofrag[i][n][r] = 0.f;

    for (int kc = 0; kc < 4; kc++) {
        const int bb = kc & 1;
        if (kc > 0) { cp_wait<0>(); }
        __syncthreads();
        if (kc < 3) { stageKV(kc + 1, bb ^ 1); cp_commit(); }

        bf16* Khb = sKV + bb*4*ATILE;
        bf16* Klb = Khb + ATILE;
        bf16* Vhb = Klb + ATILE;
        bf16* Vlb = Vhb + ATILE;

        // ---- S = Q K^T ----
        float sfr[2][8][4];
        #pragma unroll
        for (int i = 0; i < 2; i++)
            #pragma unroll
            for (int j = 0; j < 8; j++)
                #pragma unroll
                for (int r = 0; r < 4; r++) sfr[i][j][r] = 0.f;

        #pragma unroll
        for (int j = 0; j < 8; j++) {
            const int krow = wn*64 + j*8 + (lane & 7);
            uint32_t bh[2][2], bl[2][2];
            #pragma unroll
            for (int ks = 0; ks < 2; ks++) {
                const int kcol = ks*16 + (((lane >> 3) & 1) << 3);
                ldsm_x2(bh[ks], smem_u32(Khb + krow*QS + kcol));
                ldsm_x2(bl[ks], smem_u32(Klb + krow*QS + kcol));
            }
            #pragma unroll
            for (int i = 0; i < 2; i++)
                #pragma unroll
                for (int ks = 0; ks < 2; ks++) {
                    mma16816(sfr[i][j], qh[i][ks], bh[ks]);
                    mma16816(sfr[i][j], qh[i][ks], bl[ks]);
                    mma16816(sfr[i][j], ql[i][ks], bh[ks]);
                }
        }
        // scale S by 1/sqrt(DK) (exact, post-mma)
        const float sc = 0.17677669529663689f;
        #pragma unroll
        for (int i = 0; i < 2; i++)
            #pragma unroll
            for (int j = 0; j < 8; j++) {
                sfr[i][j][0] *= sc; sfr[i][j][1] *= sc;
                sfr[i][j][2] *= sc; sfr[i][j][3] *= sc;
            }

        // ---- per-row chunk max ----
        float tmax[2][2];
        #pragma unroll
        for (int i = 0; i < 2; i++) {
            tmax[i][0] = -1e30f; tmax[i][1] = -1e30f;
            #pragma unroll
            for (int j = 0; j < 8; j++) {
                tmax[i][0] = fmaxf(tmax[i][0], fmaxf(sfr[i][j][0], sfr[i][j][1]));
                tmax[i][1] = fmaxf(tmax[i][1], fmaxf(sfr[i][j][2], sfr[i][j][3]));
            }
            #pragma unroll
            for (int off = 1; off <= 2; off <<= 1) {
                tmax[i][0] = fmaxf(tmax[i][0], __shfl_xor_sync(0xffffffffu, tmax[i][0], off));
                tmax[i][1] = fmaxf(tmax[i][1], __shfl_xor_sync(0xffffffffu, tmax[i][1], off));
            }
        }
        if (lc == 0) {
            #pragma unroll
            for (int i = 0; i < 2; i++) {
                cmax[wn*128 + wm*32 + i*16 + lr]     = tmax[i][0];
                cmax[wn*128 + wm*32 + i*16 + lr + 8] = tmax[i][1];
            }
        }
        __syncthreads();

        if (warp < 4) {
            const int r = wm*32 + lane;
            float cm = fmaxf(cmax[r], cmax[128 + r]);
            float mo = m_run[r];
            float mn = fmaxf(mo, cm);
            float a  = __expf(mo - mn);
            m_run[r] = mn;
            l_run[r] *= a;
            alpha[r] = a;
        }
        __syncthreads();

        // ---- exp, psum, rescale O ----
        float mrow[2][2], arow[2][2];
        #pragma unroll
        for (int i = 0; i < 2; i++) {
            mrow[i][0] = m_run[wm*32 + i*16 + lr];
            mrow[i][1] = m_run[wm*32 + i*16 + lr + 8];
            arow[i][0] = alpha[wm*32 + i*16 + lr];
            arow[i][1] = alpha[wm*32 + i*16 + lr + 8];
        }
        float ps[2][2] = {{0.f,0.f},{0.f,0.f}};
        #pragma unroll
        for (int i = 0; i < 2; i++)
            #pragma unroll
            for (int j = 0; j < 8; j++) {
                sfr[i][j][0] = __expf(sfr[i][j][0] - mrow[i][0]);
                sfr[i][j][1] = __expf(sfr[i][j][1] - mrow[i][0]);
                sfr[i][j][2] = __expf(sfr[i][j][2] - mrow[i][1]);
                sfr[i][j][3] = __expf(sfr[i][j][3] - mrow[i][1]);
                ps[i][0] += sfr[i][j][0] + sfr[i][j][1];
                ps[i][1] += sfr[i][j][2] + sfr[i][j][3];
            }
        #pragma unroll
        for (int i = 0; i < 2; i++)
            #pragma unroll
            for (int off = 1; off <= 2; off <<= 1) {
                ps[i][0] += __shfl_xor_sync(0xffffffffu, ps[i][0], off);
                ps[i][1] += __shfl_xor_sync(0xffffffffu, ps[i][1], off);
            }
        if (lc == 0) {
            #pragma unroll
            for (int i = 0; i < 2; i++) {
                psum[wn*128 + wm*32 + i*16 + lr]     = ps[i][0];
                psum[wn*128 + wm*32 + i*16 + lr + 8] = ps[i][1];
            }
        }
        #pragma unroll
        for (int i = 0; i < 2; i++)
            #pragma unroll
            for (int n = 0; n < 4; n++) {
                ofrag[i][n][0] *= arow[i][0];
                ofrag[i][n][1] *= arow[i][0];
                ofrag[i][n][2] *= arow[i][1];
                ofrag[i][n][3] *= arow[i][1];
            }

        // ---- O += P V ----
        #pragma unroll
        for (int ks = 0; ks < 4; ks++) {
            uint32_t ah[2][4], al[2][4];
            #pragma unroll
            for (int i = 0; i < 2; i++) {
                const int j0 = 2*ks, j1 = 2*ks + 1;
                split_pack(sfr[i][j0][0], sfr[i][j0][1], ah[i][0], al[i][0]);
                split_pack(sfr[i][j0][2], sfr[i][j0][3], ah[i][1], al[i][1]);
                split_pack(sfr[i][j1][0], sfr[i][j1][1], ah[i][2], al[i][2]);
                split_pack(sfr[i][j1][2], sfr[i][j1][3], ah[i][3], al[i][3]);
            }
            const int vrow = wn*64 + ks*16 + (lane & 7) + (((lane >> 3) & 1) << 3);
            #pragma unroll
            for (int nb = 0; nb < 4; nb++) {
                uint32_t bvh[2], bvl[2];
                ldsm_x2t(bvh, smem_u32(Vhb + vrow*QS + nb*8));
                ldsm_x2t(bvl, smem_u32(Vlb + vrow*QS + nb*8));
                #pragma unroll
                for (int i = 0; i < 2; i++) {
                    mma16816(ofrag[i][nb], ah[i], bvh);
                    mma16816(ofrag[i][nb], ah[i], bvl);
                    mma16816(ofrag[i][nb], al[i], bvh);
                }
            }
        }
        __syncthreads();
        if (warp < 4) {
            const int r = wm*32 + lane;
            l_run[r] += psum[r] + psum[128 + r];
        }
        __syncthreads();
    }

    // ---- combine wn halves, normalize, split-store ----
    float* Osm = (float*)smraw;   // 16KB overlay on Q region (Q no longer needed)
    if (wn == 1) {
        #pragma unroll
        for (int i = 0; i < 2; i++)
            #pragma unroll
            for (int nb = 0; nb < 4; nb++) {
                const int rt = i*16 + lr;
                const int d  = nb*8 + lc*2;
                Osm[wm*1024 + rt*32 + d]       = ofrag[i][nb][0];
                Osm[wm*1024 + rt*32 + d + 1]   = ofrag[i][nb][1];
                Osm[wm*1024 + (rt+8)*32 + d]   = ofrag[i][nb][2];
                Osm[wm*1024 + (rt+8)*32 + d+1] = ofrag[i][nb][3];
            }
    }
    __syncthreads();
    if (wn == 0) {
        #pragma unroll
        for (int i = 0; i < 2; i++) {
            const int rt0 = i*16 + lr;
            const float li0 = 1.f / l_run[wm*32 + rt0];
            const float li1 = 1.f / l_run[wm*32 + rt0 + 8];
            #pragma unroll
            for (int nb = 0; nb < 4; nb++) {
                const int d = nb*8 + lc*2;
                float2 v0 = make_float2(
                    (ofrag[i][nb][0] + Osm[wm*1024 + rt0*32 + d])     * li0,
                    (ofrag[i][nb][1] + Osm[wm*1024 + rt0*32 + d + 1]) * li0);
                float2 v1 = make_float2(
                    (ofrag[i][nb][2] + Osm[wm*1024 + (rt0+8)*32 + d])     * li1,
                    (ofrag[i][nb][3] + Osm[wm*1024 + (rt0+8)*32 + d + 1]) * li1);
                const size_t rg = (size_t)(b*NN + q0 + wm*32 + rt0);
                uint32_t hw, lw;
                split_pack(v0.x, v0.y, hw, lw);
                *(uint32_t*)(Oh + rg*DD + h*DKK + d) = hw;
                *(uint32_t*)(Ol + rg*DD + h*DKK + d) = lw;
                split_pack(v1.x, v1.y, hw, lw);
                *(uint32_t*)(Oh + (rg+8)*DD + h*DKK + d) = hw;
                *(uint32_t*)(Ol + (rg+8)*DD + h*DKK + d) = lw;
            }
        }
    }
}

// ---------------- aggregation ------------------------------------------------
__global__ void __launch_bounds__(256) aggr_k(
    const float* __restrict__ X2, const float* __restrict__ res_W,
    const float* __restrict__ res_b, const float* __restrict__ ff_W1,
    float* __restrict__ topvec)
{
    __shared__ float g[DD];
    __shared__ float ga[DD];
    const int b = blockIdx.x, t = threadIdx.x;

    float s = 0.f;
    const float* xb = X2 + (size_t)(b*NN) * DD + t;
    for (int n = 0; n < NN; n++) s += xb[(size_t)n * DD];
    g[t] = gelu_f(s * (1.0f / NN));
    __syncthreads();

    float a = res_b[t];
    for (int i = 0; i < DD; i++) a += g[i] * res_W[(size_t)i * DD + t];
    ga[t] = gelu_f(a);
    __syncthreads();

    float tv = 0.f;
    for (int i = 0; i < DD; i++) tv += ga[i] * ff_W1[(size_t)i * DD + t];
    topvec[b * DD + t] = tv;
}

// ---------------- prototypes ------------------------------------------------
__global__ void __launch_bounds__(256) proto_k(
    const float* __restrict__ F, const int* __restrict__ labels,
    float* __restrict__ P, float* __restrict__ counts)
{
    __shared__ float Ps[CC*DD];
    __shared__ int   labs[NN];
    const int b = blockIdx.x, t = threadIdx.x;

    for (int i = t; i < CC*DD; i += 256) Ps[i] = 0.f;
    for (int i = t; i < NN; i += 256) labs[i] = labels[b*NN + i];
    __syncthreads();

    const float* fb = F + (size_t)(b*NN) * DD + t;
    for (int n = 0; n < NN; n++)
        Ps[labs[n]*DD + t] += fb[(size_t)n * DD];
    __syncthreads();

    for (int i = t; i < CC*DD; i += 256) P[(size_t)b*CC*DD + i] = Ps[i];
    if (t < CC) {
        int cnt = 0;
        for (int n = 0; n < NN; n++) cnt += (labs[n] == t);
        counts[b*CC + t] = (float)cnt;
    }
}

// ---------------- scoring ---------------------------------------------------
__global__ void __launch_bounds__(256) score_k(
    const float* __restrict__ F, const float* __restrict__ P,
    const float* __restrict__ counts, const int* __restrict__ labels,
    float* __restrict__ out)
{
    __shared__ float Ps[CC*DD];
    __shared__ float cs[CC];
    const int b = blockIdx.y;
    for (int i = threadIdx.x; i < CC*DD; i += 256) Ps[i] = P[(size_t)b*CC*DD + i];
    if (threadIdx.x < CC) cs[threadIdx.x] = counts[b*CC + threadIdx.x];
    __syncthreads();

    const int warp = threadIdx.x >> 5, lane = threadIdx.x & 31;
    const int n = blockIdx.x * 8 + warp;
    const float* f = F + (size_t)(b*NN + n) * DD;

    float dot[CC];
    #pragma unroll
    for (int c = 0; c < CC; c++) dot[c] = 0.f;
    float nrm = 0.f;

    for (int d = lane; d < DD; d += 32) {
        float fv = f[d];
        nrm += fv * fv;
        #pragma unroll
        for (int c = 0; c < CC; c++) dot[c] += fv * Ps[c*DD + d];
    }
    #pragma unroll
    for (int off = 16; off > 0; off >>= 1) {
        nrm += __shfl_xor_sync(0xffffffffu, nrm, off);
        #pragma unroll
        for (int c = 0; c < CC; c++)
            dot[c] += __shfl_xor_sync(0xffffffffu, dot[c], off);
    }
    if (lane < CC) {
        const int c = lane;
        const int lab = labels[b*NN + n];
        const float mm = (lab == c) ? 1.f : 0.f;
        out[(size_t)(b*NN + n) * CC + c] = (dot[c] - mm * nrm) / (cs[c] - mm);
    }
}

// ---------------- launcher -------------------------------------------------
extern "C" void kernel_launch(void* const* d_in, const int* in_sizes, int n_in,
                              void* d_out, int out_size)
{
    const float* emb    = (const float*)d_in[0];
    const int*   labels = (const int*)  d_in[1];
    const float* Wq0 = (const float*)d_in[2];
    const float* Wk0 = (const float*)d_in[3];
    const float* Wv0 = (const float*)d_in[4];
    const float* Wo0 = (const float*)d_in[5];
    const float* Wq1 = (const float*)d_in[6];
    const float* Wk1 = (const float*)d_in[7];
    const float* Wv1 = (const float*)d_in[8];
    const float* Wo1 = (const float*)d_in[9];
    const float* res_W = (const float*)d_in[10];
    const float* res_b = (const float*)d_in[11];
    const float* ff_W1 = (const float*)d_in[12];
    const float* ff_b1 = (const float*)d_in[13];
    const float* ff_W2 = (const float*)d_in[14];
    const float* ff_b2 = (const float*)d_in[15];
    float* out = (float*)d_out;

    bf16 *emb_h, *emb_l, *gemb_h, *gemb_l, *W_h, *W_l, *QKV_h, *QKV_l;
    bf16 *pA_h, *pA_l, *pB_h, *pB_l;
    float *X32, *tv, *P, *cnt;
    cudaGetSymbolAddress((void**)&emb_h,  g_emb_h);
    cudaGetSymbolAddress((void**)&emb_l,  g_emb_l);
    cudaGetSymbolAddress((void**)&gemb_h, g_gemb_h);
    cudaGetSymbolAddress((void**)&gemb_l, g_gemb_l);
    cudaGetSymbolAddress((void**)&W_h,    g_W_h);
    cudaGetSymbolAddress((void**)&W_l,    g_W_l);
    cudaGetSymbolAddress((void**)&QKV_h,  g_QKV_h);
    cudaGetSymbolAddress((void**)&QKV_l,  g_QKV_l);
    cudaGetSymbolAddress((void**)&pA_h,   g_pA_h);
    cudaGetSymbolAddress((void**)&pA_l,   g_pA_l);
    cudaGetSymbolAddress((void**)&pB_h,   g_pB_h);
    cudaGetSymbolAddress((void**)&pB_l,   g_pB_l);
    cudaGetSymbolAddress((void**)&X32,    g_X32);
    cudaGetSymbolAddress((void**)&tv,     g_topvec);
    cudaGetSymbolAddress((void**)&P,      g_P);
    cudaGetSymbolAddress((void**)&cnt,    g_counts);

    constexpr int SM128 = GCfg<128>::SMEM;   // 75776
    constexpr int SM64  = GCfg<64>::SMEM;    // 59392
    cudaFuncSetAttribute(gemm2_k<128,false,false,false,true >, cudaFuncAttributeMaxDynamicSharedMemorySize, SM128);
    cudaFuncSetAttribute(gemm2_k<64 ,true ,false,false,true >, cudaFuncAttributeMaxDynamicSharedMemorySize, SM64);
    cudaFuncSetAttribute(gemm2_k<64 ,false,false,false,false>, cudaFuncAttributeMaxDynamicSharedMemorySize, SM64);
    cudaFuncSetAttribute(gemm2_k<64 ,true ,true ,true ,true >, cudaFuncAttributeMaxDynamicSharedMemorySize, SM64);
    cudaFuncSetAttribute(gemm2_k<64 ,false,true ,false,false>, cudaFuncAttributeMaxDynamicSharedMemorySize, SM64);
    cudaFuncSetAttribute(attn2_k, cudaFuncAttributeMaxDynamicSharedMemorySize, ATTN_SMEM);

    const dim3 g3(6, 64);    // fused QKV, BN=128: 3 mats x 2 col-tiles
    const dim3 g1(4, 64);    // single GEMM, BN=64: 4 col-tiles
    const dim3 ag(NN/128, HH, BB);

    // ---- prep: split emb/gelu(emb)/weights ----
    prep_k<<<2688, 256>>>(emb, Wq0, Wk0, Wv0, Wo0, Wq1, Wk1, Wv1, Wo1, ff_W1, ff_W2);

    // ---- MHA 0 ----
    gemm2_k<128,false,false,false,true ><<<g3, 256, SM128>>>(emb_h, emb_l, W_h, W_l, QKV_h, QKV_l, nullptr, nullptr, nullptr);
    attn2_k<<<ag, 256, ATTN_SMEM>>>(QKV_h, QKV_l, pA_h, pA_l);
    gemm2_k<64 ,true ,false,false,true ><<<g1, 256, SM64>>>(pA_h, pA_l, W_h + 3*DD*DD, W_l + 3*DD*DD, pB_h, pB_l, nullptr, nullptr, nullptr);

    // ---- MHA 1 ----
    gemm2_k<128,false,false,false,true ><<<g3, 256, SM128>>>(pB_h, pB_l, W_h + 4*DD*DD, W_l + 4*DD*DD, QKV_h, QKV_l, nullptr, nullptr, nullptr);
    attn2_k<<<ag, 256, ATTN_SMEM>>>(QKV_h, QKV_l, pA_h, pA_l);
    gemm2_k<64 ,false,false,false,false><<<g1, 256, SM64>>>(pA_h, pA_l, W_h + 7*DD*DD, W_l + 7*DD*DD, nullptr, nullptr, X32, nullptr, nullptr);

    // ---- aggregation ----
    aggr_k<<<BB, 256>>>(X32, res_W, res_b, ff_W1, tv);

    // ---- FF ----
    gemm2_k<64 ,true ,true ,true ,true ><<<g1, 256, SM64>>>(gemb_h, gemb_l, W_h + 8*DD*DD, W_l + 8*DD*DD, pB_h, pB_l, nullptr, ff_b1, tv);
    gemm2_k<64 ,false,true ,false,false><<<g1, 256, SM64>>>(pB_h, pB_l, W_h + 9*DD*DD, W_l + 9*DD*DD, nullptr, nullptr, X32, ff_b2, nullptr);

    // ---- prototypes + scoring ----
    proto_k<<<BB, 256>>>(X32, labels, P, cnt);
    score_k<<<dim3(NN/8, BB), 256>>>(X32, P, cnt, labels, out);
}

// round 16
// speedup vs baseline: 1.0686x; 1.0411x over previous
#include <cuda_runtime.h>
#include <cuda_bf16.h>
#include <math.h>
#include <stdint.h>

#define BB   16
#define NN   512
#define DD   256
#define HH   8
#define DKK  32
#define CC   16
#define MTOT (BB*NN)   // 8192
typedef __nv_bfloat16 bf16;

// ---------------- scratch (device globals: no allocation allowed) ----------
__device__ __align__(16) bf16 g_emb_h[MTOT*DD],  g_emb_l[MTOT*DD];
__device__ __align__(16) bf16 g_gemb_h[MTOT*DD], g_gemb_l[MTOT*DD];
__device__ __align__(16) bf16 g_W_h[10*DD*DD],   g_W_l[10*DD*DD];
__device__ __align__(16) bf16 g_QKV_h[3*MTOT*DD], g_QKV_l[3*MTOT*DD];
__device__ __align__(16) bf16 g_pA_h[MTOT*DD],  g_pA_l[MTOT*DD];
__device__ __align__(16) bf16 g_pB_h[MTOT*DD],  g_pB_l[MTOT*DD];
__device__ float g_X32[MTOT*DD];
__device__ float g_topvec[BB*DD];
__device__ float g_P[BB*CC*DD];
__device__ float g_counts[BB*CC];

__device__ __forceinline__ float gelu_f(float x) {
    return 0.5f * x * (1.0f + erff(x * 0.7071067811865475f));
}

// ---------------- helpers ----------------------------------------------
__device__ __forceinline__ uint32_t smem_u32(const void* p) {
    return (uint32_t)__cvta_generic_to_shared(p);
}
__device__ __forceinline__ void cp16(void* dst, const void* src) {
    asm volatile("cp.async.cg.shared.global [%0], [%1], 16;"
                 :: "r"(smem_u32(dst)), "l"(src));
}
__device__ __forceinline__ void cp_commit() { asm volatile("cp.async.commit_group;"); }
template<int N> __device__ __forceinline__ void cp_wait() {
    asm volatile("cp.async.wait_group %0;" :: "n"(N));
}
__device__ __forceinline__ void ldsm_x4(uint32_t* r, uint32_t addr) {
    asm volatile("ldmatrix.sync.aligned.m8n8.x4.shared.b16 {%0,%1,%2,%3}, [%4];"
                 : "=r"(r[0]), "=r"(r[1]), "=r"(r[2]), "=r"(r[3]) : "r"(addr));
}
__device__ __forceinline__ void ldsm_x2(uint32_t* r, uint32_t addr) {
    asm volatile("ldmatrix.sync.aligned.m8n8.x2.shared.b16 {%0,%1}, [%2];"
                 : "=r"(r[0]), "=r"(r[1]) : "r"(addr));
}
__device__ __forceinline__ void ldsm_x2t(uint32_t* r, uint32_t addr) {
    asm volatile("ldmatrix.sync.aligned.m8n8.x2.trans.shared.b16 {%0,%1}, [%2];"
                 : "=r"(r[0]), "=r"(r[1]) : "r"(addr));
}
__device__ __forceinline__ void mma16816(float* d, const uint32_t* a, const uint32_t* b) {
    asm volatile(
        "mma.sync.aligned.m16n8k16.row.col.f32.bf16.bf16.f32 "
        "{%0,%1,%2,%3}, {%4,%5,%6,%7}, {%8,%9}, {%0,%1,%2,%3};"
        : "+f"(d[0]), "+f"(d[1]), "+f"(d[2]), "+f"(d[3])
        : "r"(a[0]), "r"(a[1]), "r"(a[2]), "r"(a[3]), "r"(b[0]), "r"(b[1]));
}
__device__ __forceinline__ void split_pack(float x, float y, uint32_t& hi, uint32_t& lo) {
    __nv_bfloat16 hx = __float2bfloat16(x);
    __nv_bfloat16 hy = __float2bfloat16(y);
    __nv_bfloat16 lx = __float2bfloat16(x - __bfloat162float(hx));
    __nv_bfloat16 ly = __float2bfloat16(y - __bfloat162float(hy));
    __nv_bfloat162 H(hx, hy), L(lx, ly);
    hi = *(uint32_t*)&H;
    lo = *(uint32_t*)&L;
}
__device__ __forceinline__ void split4(float4 v, uint2& h, uint2& l) {
    uint32_t h0, l0, h1, l1;
    split_pack(v.x, v.y, h0, l0);
    split_pack(v.z, v.w, h1, l1);
    h = make_uint2(h0, h1);
    l = make_uint2(l0, l1);
}

// ---------------- prep: split emb, gelu(emb), and 10 weights once ----------
#define EMB_QUADS (MTOT*DD/4)      // 524288
__global__ void __launch_bounds__(256) prep_k(
    const float* __restrict__ emb,
    const float* __restrict__ Wq0, const float* __restrict__ Wk0,
    const float* __restrict__ Wv0, const float* __restrict__ Wo0,
    const float* __restrict__ Wq1, const float* __restrict__ Wk1,
    const float* __restrict__ Wv1, const float* __restrict__ Wo1,
    const float* __restrict__ ffW1, const float* __restrict__ ffW2)
{
    int idx = blockIdx.x * 256 + threadIdx.x;
    if (idx < EMB_QUADS) {
        float4 v = ((const float4*)emb)[idx];
        uint2 h, l;
        split4(v, h, l);
        *(uint2*)(g_emb_h + idx*4) = h;
        *(uint2*)(g_emb_l + idx*4) = l;
        v.x = gelu_f(v.x); v.y = gelu_f(v.y); v.z = gelu_f(v.z); v.w = gelu_f(v.w);
        split4(v, h, l);
        *(uint2*)(g_gemb_h + idx*4) = h;
        *(uint2*)(g_gemb_l + idx*4) = l;
    } else {
        int w = idx - EMB_QUADS;
        int mat = w >> 14;          // 16384 quads per 256x256 matrix
        int off = w & 16383;
        const float* src;
        switch (mat) {
            case 0: src = Wq0; break;  case 1: src = Wk0; break;
            case 2: src = Wv0; break;  case 3: src = Wo0; break;
            case 4: src = Wq1; break;  case 5: src = Wk1; break;
            case 6: src = Wv1; break;  case 7: src = Wo1; break;
            case 8: src = ffW1 + DD*DD; break;   // bottom half of ff_W1
            default: src = ffW2; break;
        }
        float4 v = ((const float4*)src)[off];
        uint2 h, l;
        split4(v, h, l);
        *(uint2*)(g_W_h + mat*DD*DD + off*4) = h;
        *(uint2*)(g_W_l + mat*DD*DD + off*4) = l;
    }
}

// ---------------- cp.async double-buffered bf16-split GEMM ------------------
// Block tile 128 x BN, 8 warps 4M x 2N, K-step 32. BN in {64,128}.
#define A_STR 40
#define ASZ (128*A_STR)    // 5120 elems
template<int BN>
struct GCfg {
    static constexpr int B_STR = BN + 8;
    static constexpr int WSZ   = 32 * B_STR;
    static constexpr int NJ    = BN / 16;           // j-blocks per warp
    static constexpr int SMEM  = (2*ASZ*2 + 2*WSZ*2) * 2;  // bytes
    static constexpr int NCT   = DD / BN;           // col tiles per matrix
};
template<int BN, bool GO, bool HB, bool HE, bool SPLIT>
__global__ void __launch_bounds__(256, 2) gemm2_k(
    const bf16* __restrict__ Ah, const bf16* __restrict__ Al,
    const bf16* __restrict__ Wh, const bf16* __restrict__ Wl,
    bf16* __restrict__ Ch, bf16* __restrict__ Cl, float* __restrict__ Cf,
    const float* __restrict__ bias, const float* __restrict__ epvec)
{
    constexpr int B_STR = GCfg<BN>::B_STR;
    constexpr int WSZ   = GCfg<BN>::WSZ;
    constexpr int NJ    = GCfg<BN>::NJ;
    constexpr int NCT   = GCfg<BN>::NCT;

    extern __shared__ char sm[];
    bf16* sAh = (bf16*)sm;
    bf16* sAl = sAh + 2*ASZ;
    bf16* sWh = sAl + 2*ASZ;
    bf16* sWl = sWh + 2*WSZ;

    const int tid  = threadIdx.x;
    const int warp = tid >> 5, lane = tid & 31;
    const int wm = warp & 3, wn = warp >> 2;
    const int mat  = blockIdx.x / NCT;
    const int col0 = (blockIdx.x % NCT) * BN;
    const int row0 = blockIdx.y * 128;
    Wh += (size_t)mat * DD * DD;
    Wl += (size_t)mat * DD * DD;
    const size_t cofs = (size_t)mat * MTOT * DD;

    float acc[2][NJ][4];
    #pragma unroll
    for (int i = 0; i < 2; i++)
        #pragma unroll
        for (int j = 0; j < NJ; j++)
            #pragma unroll
            for (int r = 0; r < 4; r++) acc[i][j][r] = 0.f;

    const int a_r_off = lane & 15;
    const int a_c_off = (lane >> 4) << 3;
    const int b_k_off = lane & 15;

    auto stage = [&](int kt, int bb) {
        #pragma unroll
        for (int c = tid; c < 512; c += 256) {
            const int ar = c >> 2, ac = (c & 3) * 8;
            const size_t ao = (size_t)(row0 + ar) * DD + kt*32 + ac;
            cp16(sAh + bb*ASZ + ar*A_STR + ac, Ah + ao);
            cp16(sAl + bb*ASZ + ar*A_STR + ac, Al + ao);
        }
        #pragma unroll
        for (int c = tid; c < BN*4; c += 256) {
            const int wk = c / (BN/8), wc = (c % (BN/8)) * 8;
            const size_t wo = (size_t)(kt*32 + wk) * DD + col0 + wc;
            cp16(sWh + bb*WSZ + wk*B_STR + wc, Wh + wo);
            cp16(sWl + bb*WSZ + wk*B_STR + wc, Wl + wo);
        }
    };

    stage(0, 0);
    cp_commit();

    for (int kt = 0; kt < 8; kt++) {
        const int bb = kt & 1;
        cp_wait<0>();
        __syncthreads();
        if (kt < 7) { stage(kt + 1, bb ^ 1); cp_commit(); }

        #pragma unroll
        for (int kk = 0; kk < 32; kk += 16) {
            uint32_t ah[2][4], al[2][4];
            #pragma unroll
            for (int i = 0; i < 2; i++) {
                const int r = wm*32 + i*16 + a_r_off;
                const int c = kk + a_c_off;
                ldsm_x4(ah[i], smem_u32(sAh + bb*ASZ + r*A_STR + c));
                ldsm_x4(al[i], smem_u32(sAl + bb*ASZ + r*A_STR + c));
            }
            #pragma unroll
            for (int j = 0; j < NJ; j++) {
                const int n  = wn*(BN/2) + j*8;
                const int kr = kk + b_k_off;
                uint32_t bh[2], bl[2];
                ldsm_x2t(bh, smem_u32(sWh + bb*WSZ + kr*B_STR + n));
                ldsm_x2t(bl, smem_u32(sWl + bb*WSZ + kr*B_STR + n));
                #pragma unroll
                for (int i = 0; i < 2; i++) {
                    mma16816(acc[i][j], ah[i], bh);
                    mma16816(acc[i][j], ah[i], bl);
                    mma16816(acc[i][j], al[i], bh);
                }
            }
        }
    }

    // ---- epilogue ----
    const int b = row0 >> 9;
    #pragma unroll
    for (int i = 0; i < 2; i++) {
        #pragma unroll
        for (int j = 0; j < NJ; j++) {
            const int rbase = row0 + wm*32 + i*16 + (lane >> 2);
            const int cbase = col0 + wn*(BN/2) + j*8 + ((lane & 3) << 1);
            float2 v0 = make_float2(acc[i][j][0], acc[i][j][1]);
            float2 v1 = make_float2(acc[i][j][2], acc[i][j][3]);
            if (HB) {
                float2 bv = *(const float2*)(bias + cbase);
                v0.x += bv.x; v0.y += bv.y; v1.x += bv.x; v1.y += bv.y;
            }
            if (HE) {
                float2 ev = *(const float2*)(epvec + b * DD + cbase);
                v0.x += ev.x; v0.y += ev.y; v1.x += ev.x; v1.y += ev.y;
            }
            if (GO) {
                v0.x = gelu_f(v0.x); v0.y = gelu_f(v0.y);
                v1.x = gelu_f(v1.x); v1.y = gelu_f(v1.y);
            }
            const size_t o0 = cofs + (size_t)rbase * DD + cbase;
            const size_t o1 = cofs + (size_t)(rbase + 8) * DD + cbase;
            if (SPLIT) {
                uint32_t hw, lw;
                split_pack(v0.x, v0.y, hw, lw);
                *(uint32_t*)(Ch + o0) = hw;  *(uint32_t*)(Cl + o0) = lw;
                split_pack(v1.x, v1.y, hw, lw);
                *(uint32_t*)(Ch + o1) = hw;  *(uint32_t*)(Cl + o1) = lw;
            } else {
                *(float2*)(Cf + o0) = v0;
                *(float2*)(Cf + o1) = v1;
            }
        }
    }
}

// ---------------- sync-free tensor-core flash attention ---------------------
// 8 warps; warp w owns q-rows [w*16, w*16+16) vs ALL keys. Softmax stats are
// warp-local (shfl over the 4 lanes sharing a row). One sync per KV chunk.
#define QS 40
#define ATILE (128*QS)            // 5120 elems / 10240 B
#define ATTN_SMEM (10*ATILE*2)    // 102400 B
__global__ void __launch_bounds__(256, 1) attn3_k(
    const bf16* __restrict__ QKVh, const bf16* __restrict__ QKVl,
    bf16* __restrict__ Oh, bf16* __restrict__ Ol)
{
    extern __shared__ char smraw[];
    bf16* sQh = (bf16*)smraw;
    bf16* sQl = sQh + ATILE;
    bf16* sKV = sQl + ATILE;       // [buf][Kh,Kl,Vh,Vl] tiles

    const int tid  = threadIdx.x;
    const int warp = tid >> 5, lane = tid & 31;
    const int lr = lane >> 2, lc = lane & 3;
    const int b = blockIdx.z, h = blockIdx.y;
    const int q0 = blockIdx.x * 128;
    const size_t KOFF = (size_t)MTOT * DD;
    const size_t VOFF = 2 * KOFF;

    // ---- stage Q ----
    {
        const size_t base = (size_t)(b*NN + q0) * DD + h * DKK;
        #pragma unroll
        for (int c = tid; c < 512; c += 256) {
            const int r = c >> 2, cc = (c & 3) * 8;
            const size_t so = base + (size_t)r * DD + cc;
            cp16(sQh + r*QS + cc, QKVh + so);
            cp16(sQl + r*QS + cc, QKVl + so);
        }
    }
    auto stageKV = [&](int kc, int bufb) {
        const size_t base = (size_t)(b*NN + kc*128) * DD + h * DKK;
        bf16* dKh = sKV + bufb*4*ATILE;
        bf16* dKl = dKh + ATILE;
        bf16* dVh = dKl + ATILE;
        bf16* dVl = dVh + ATILE;
        #pragma unroll
        for (int c = tid; c < 512; c += 256) {
            const int r = c >> 2, cc = (c & 3) * 8;
            const size_t so = base + (size_t)r * DD + cc;
            cp16(dKh + r*QS + cc, QKVh + KOFF + so);
            cp16(dKl + r*QS + cc, QKVl + KOFF + so);
            cp16(dVh + r*QS + cc, QKVh + VOFF + so);
            cp16(dVl + r*QS + cc, QKVl + VOFF + so);
        }
    };
    stageKV(0, 0);
    cp_commit();
    cp_wait<0>();
    __syncthreads();

    // ---- Q fragments (warp's 16 rows, k=32) ----
    uint32_t qh[2][4], ql[2][4];
    #pragma unroll
    for (int ks = 0; ks < 2; ks++) {
        const int r = warp*16 + (lane & 15);
        const int c = ks*16 + ((lane >> 4) << 3);
        ldsm_x4(qh[ks], smem_u32(sQh + r*QS + c));
        ldsm_x4(ql[ks], smem_u32(sQl + r*QS + c));
    }

    float m0 = -1e30f, m1 = -1e30f, l0 = 0.f, l1 = 0.f;
    float ofrag[4][4];
    #pragma unroll
    for (int n = 0; n < 4; n++)
        #pragma unroll
        for (int r = 0; r < 4; r++) ofrag[n][r] = 0.f;

    for (int kc = 0; kc < 4; kc++) {
        const int bb = kc & 1;
        if (kc > 0) {
            cp_wait<0>();
            __syncthreads();
        }
        if (kc < 3) { stageKV(kc + 1, bb ^ 1); cp_commit(); }

        bf16* Khb = sKV + bb*4*ATILE;
        bf16* Klb = Khb + ATILE;
        bf16* Vhb = Klb + ATILE;
        bf16* Vlb = Vhb + ATILE;

        // ---- S = Q K^T over all 128 keys (16 n-blocks) ----
        float sfr[16][4];
        #pragma unroll
        for (int j = 0; j < 16; j++)
            #pragma unroll
            for (int r = 0; r < 4; r++) sfr[j][r] = 0.f;

        #pragma unroll
        for (int j = 0; j < 16; j++) {
            const int krow = j*8 + (lane & 7);
            uint32_t bh[2][2], bl[2][2];
            #pragma unroll
            for (int ks = 0; ks < 2; ks++) {
                const int kcol = ks*16 + (((lane >> 3) & 1) << 3);
                ldsm_x2(bh[ks], smem_u32(Khb + krow*QS + kcol));
                ldsm_x2(bl[ks], smem_u32(Klb + krow*QS + kcol));
            }
            #pragma unroll
            for (int ks = 0; ks < 2; ks++) {
                mma16816(sfr[j], qh[ks], bh[ks]);
                mma16816(sfr[j], qh[ks], bl[ks]);
                mma16816(sfr[j], ql[ks], bh[ks]);
            }
        }
        const float sc = 0.17677669529663689f;
        #pragma unroll
        for (int j = 0; j < 16; j++) {
            sfr[j][0] *= sc; sfr[j][1] *= sc;
            sfr[j][2] *= sc; sfr[j][3] *= sc;
        }

        // ---- warp-local row max (4 lanes share a row) ----
        float cm0 = -1e30f, cm1 = -1e30f;
        #pragma unroll
        for (int j = 0; j < 16; j++) {
            cm0 = fmaxf(cm0, fmaxf(sfr[j][0], sfr[j][1]));
            cm1 = fmaxf(cm1, fmaxf(sfr[j][2], sfr[j][3]));
        }
        #pragma unroll
        for (int off = 1; off <= 2; off <<= 1) {
            cm0 = fmaxf(cm0, __shfl_xor_sync(0xffffffffu, cm0, off));
            cm1 = fmaxf(cm1, __shfl_xor_sync(0xffffffffu, cm1, off));
        }
        const float mn0 = fmaxf(m0, cm0);
        const float mn1 = fmaxf(m1, cm1);
        const float a0 = __expf(m0 - mn0);
        const float a1 = __expf(m1 - mn1);
        m0 = mn0; m1 = mn1;
        l0 *= a0;  l1 *= a1;

        // ---- p = exp(s-m); row sums; rescale O ----
        float ps0 = 0.f, ps1 = 0.f;
        #pragma unroll
        for (int j = 0; j < 16; j++) {
            sfr[j][0] = __expf(sfr[j][0] - m0);
            sfr[j][1] = __expf(sfr[j][1] - m0);
            sfr[j][2] = __expf(sfr[j][2] - m1);
            sfr[j][3] = __expf(sfr[j][3] - m1);
            ps0 += sfr[j][0] + sfr[j][1];
            ps1 += sfr[j][2] + sfr[j][3];
        }
        #pragma unroll
        for (int off = 1; off <= 2; off <<= 1) {
            ps0 += __shfl_xor_sync(0xffffffffu, ps0, off);
            ps1 += __shfl_xor_sync(0xffffffffu, ps1, off);
        }
        l0 += ps0;  l1 += ps1;
        #pragma unroll
        for (int n = 0; n < 4; n++) {
            ofrag[n][0] *= a0; ofrag[n][1] *= a0;
            ofrag[n][2] *= a1; ofrag[n][3] *= a1;
        }

        // ---- O += P V over 8 k-blocks of 16 keys ----
        #pragma unroll
        for (int ks = 0; ks < 8; ks++) {
            uint32_t ah[4], al[4];
            const int j0 = 2*ks, j1 = 2*ks + 1;
            split_pack(sfr[j0][0], sfr[j0][1], ah[0], al[0]);
            split_pack(sfr[j0][2], sfr[j0][3], ah[1], al[1]);
            split_pack(sfr[j1][0], sfr[j1][1], ah[2], al[2]);
            split_pack(sfr[j1][2], sfr[j1][3], ah[3], al[3]);
            const int vrow = ks*16 + (lane & 7) + (((lane >> 3) & 1) << 3);
            #pragma unroll
            for (int nb = 0; nb < 4; nb++) {
                uint32_t bvh[2], bvl[2];
                ldsm_x2t(bvh, smem_u32(Vhb + vrow*QS + nb*8));
                ldsm_x2t(bvl, smem_u32(Vlb + vrow*QS + nb*8));
                mma16816(ofrag[nb], ah, bvh);
                mma16816(ofrag[nb], ah, bvl);
                mma16816(ofrag[nb], al, bvh);
            }
        }
    }

    // ---- normalize, split-store (warp-local) ----
    const float li0 = 1.f / l0;
    const float li1 = 1.f / l1;
    const size_t rg = (size_t)(b*NN + q0 + warp*16 + lr);
    #pragma unroll
    for (int nb = 0; nb < 4; nb++) {
        const int d = nb*8 + lc*2;
        uint32_t hw, lw;
        split_pack(ofrag[nb][0]*li0, ofrag[nb][1]*li0, hw, lw);
        *(uint32_t*)(Oh + rg*DD + h*DKK + d) = hw;
        *(uint32_t*)(Ol + rg*DD + h*DKK + d) = lw;
        split_pack(ofrag[nb][2]*li1, ofrag[nb][3]*li1, hw, lw);
        *(uint32_t*)(Oh + (rg+8)*DD + h*DKK + d) = hw;
        *(uint32_t*)(Ol + (rg+8)*DD + h*DKK + d) = lw;
    }
}

// ---------------- aggregation ------------------------------------------------
__global__ void __launch_bounds__(256) aggr_k(
    const float* __restrict__ X2, const float* __restrict__ res_W,
    const float* __restrict__ res_b, const float* __restrict__ ff_W1,
    float* __restrict__ topvec)
{
    __shared__ float g[DD];
    __shared__ float ga[DD];
    const int b = blockIdx.x, t = threadIdx.x;

    float s = 0.f;
    const float* xb = X2 + (size_t)(b*NN) * DD + t;
    for (int n = 0; n < NN; n++) s += xb[(size_t)n * DD];
    g[t] = gelu_f(s * (1.0f / NN));
    __syncthreads();

    float a = res_b[t];
    for (int i = 0; i < DD; i++) a += g[i] * res_W[(size_t)i * DD + t];
    ga[t] = gelu_f(a);
    __syncthreads();

    float tv = 0.f;
    for (int i = 0; i < DD; i++) tv += ga[i] * ff_W1[(size_t)i * DD + t];
    topvec[b * DD + t] = tv;
}

// ---------------- prototypes ------------------------------------------------
__global__ void __launch_bounds__(256) proto_k(
    const float* __restrict__ F, const int* __restrict__ labels,
    float* __restrict__ P, float* __restrict__ counts)
{
    __shared__ float Ps[CC*DD];
    __shared__ int   labs[NN];
    const int b = blockIdx.x, t = threadIdx.x;

    for (int i = t; i < CC*DD; i += 256) Ps[i] = 0.f;
    for (int i = t; i < NN; i += 256) labs[i] = labels[b*NN + i];
    __syncthreads();

    const float* fb = F + (size_t)(b*NN) * DD + t;
    for (int n = 0; n < NN; n++)
        Ps[labs[n]*DD + t] += fb[(size_t)n * DD];
    __syncthreads();

    for (int i = t; i < CC*DD; i += 256) P[(size_t)b*CC*DD + i] = Ps[i];
    if (t < CC) {
        int cnt = 0;
        for (int n = 0; n < NN; n++) cnt += (labs[n] == t);
        counts[b*CC + t] = (float)cnt;
    }
}

// ---------------- scoring ---------------------------------------------------
__global__ void __launch_bounds__(256) score_k(
    const float* __restrict__ F, const float* __restrict__ P,
    const float* __restrict__ counts, const int* __restrict__ labels,
    float* __restrict__ out)
{
    __shared__ float Ps[CC*DD];
    __shared__ float cs[CC];
    const int b = blockIdx.y;
    for (int i = threadIdx.x; i < CC*DD; i += 256) Ps[i] = P[(size_t)b*CC*DD + i];
    if (threadIdx.x < CC) cs[threadIdx.x] = counts[b*CC + threadIdx.x];
    __syncthreads();

    const int warp = threadIdx.x >> 5, lane = threadIdx.x & 31;
    const int n = blockIdx.x * 8 + warp;
    const float* f = F + (size_t)(b*NN + n) * DD;

    float dot[CC];
    #pragma unroll
    for (int c = 0; c < CC; c++) dot[c] = 0.f;
    float nrm = 0.f;

    for (int d = lane; d < DD; d += 32) {
        float fv = f[d];
        nrm += fv * fv;
        #pragma unroll
        for (int c = 0; c < CC; c++) dot[c] += fv * Ps[c*DD + d];
    }
    #pragma unroll
    for (int off = 16; off > 0; off >>= 1) {
        nrm += __shfl_xor_sync(0xffffffffu, nrm, off);
        #pragma unroll
        for (int c = 0; c < CC; c++)
            dot[c] += __shfl_xor_sync(0xffffffffu, dot[c], off);
    }
    if (lane < CC) {
        const int c = lane;
        const int lab = labels[b*NN + n];
        const float mm = (lab == c) ? 1.f : 0.f;
        out[(size_t)(b*NN + n) * CC + c] = (dot[c] - mm * nrm) / (cs[c] - mm);
    }
}

// ---------------- launcher -------------------------------------------------
extern "C" void kernel_launch(void* const* d_in, const int* in_sizes, int n_in,
                              void* d_out, int out_size)
{
    const float* emb    = (const float*)d_in[0];
    const int*   labels = (const int*)  d_in[1];
    const float* Wq0 = (const float*)d_in[2];
    const float* Wk0 = (const float*)d_in[3];
    const float* Wv0 = (const float*)d_in[4];
    const float* Wo0 = (const float*)d_in[5];
    const float* Wq1 = (const float*)d_in[6];
    const float* Wk1 = (const float*)d_in[7];
    const float* Wv1 = (const float*)d_in[8];
    const float* Wo1 = (const float*)d_in[9];
    const float* res_W = (const float*)d_in[10];
    const float* res_b = (const float*)d_in[11];
    const float* ff_W1 = (const float*)d_in[12];
    const float* ff_b1 = (const float*)d_in[13];
    const float* ff_W2 = (const float*)d_in[14];
    const float* ff_b2 = (const float*)d_in[15];
    float* out = (float*)d_out;

    bf16 *emb_h, *emb_l, *gemb_h, *gemb_l, *W_h, *W_l, *QKV_h, *QKV_l;
    bf16 *pA_h, *pA_l, *pB_h, *pB_l;
    float *X32, *tv, *P, *cnt;
    cudaGetSymbolAddress((void**)&emb_h,  g_emb_h);
    cudaGetSymbolAddress((void**)&emb_l,  g_emb_l);
    cudaGetSymbolAddress((void**)&gemb_h, g_gemb_h);
    cudaGetSymbolAddress((void**)&gemb_l, g_gemb_l);
    cudaGetSymbolAddress((void**)&W_h,    g_W_h);
    cudaGetSymbolAddress((void**)&W_l,    g_W_l);
    cudaGetSymbolAddress((void**)&QKV_h,  g_QKV_h);
    cudaGetSymbolAddress((void**)&QKV_l,  g_QKV_l);
    cudaGetSymbolAddress((void**)&pA_h,   g_pA_h);
    cudaGetSymbolAddress((void**)&pA_l,   g_pA_l);
    cudaGetSymbolAddress((void**)&pB_h,   g_pB_h);
    cudaGetSymbolAddress((void**)&pB_l,   g_pB_l);
    cudaGetSymbolAddress((void**)&X32,    g_X32);
    cudaGetSymbolAddress((void**)&tv,     g_topvec);
    cudaGetSymbolAddress((void**)&P,      g_P);
    cudaGetSymbolAddress((void**)&cnt,    g_counts);

    constexpr int SM128 = GCfg<128>::SMEM;   // 75776
    constexpr int SM64  = GCfg<64>::SMEM;    // 59392
    cudaFuncSetAttribute(gemm2_k<128,false,false,false,true >, cudaFuncAttributeMaxDynamicSharedMemorySize, SM128);
    cudaFuncSetAttribute(gemm2_k<64 ,true ,false,false,true >, cudaFuncAttributeMaxDynamicSharedMemorySize, SM64);
    cudaFuncSetAttribute(gemm2_k<64 ,false,false,false,false>, cudaFuncAttributeMaxDynamicSharedMemorySize, SM64);
    cudaFuncSetAttribute(gemm2_k<64 ,true ,true ,true ,true >, cudaFuncAttributeMaxDynamicSharedMemorySize, SM64);
    cudaFuncSetAttribute(gemm2_k<64 ,false,true ,false,false>, cudaFuncAttributeMaxDynamicSharedMemorySize, SM64);
    cudaFuncSetAttribute(attn3_k, cudaFuncAttributeMaxDynamicSharedMemorySize, ATTN_SMEM);

    const dim3 g3(6, 64);    // fused QKV, BN=128: 3 mats x 2 col-tiles
    const dim3 g1(4, 64);    // single GEMM, BN=64: 4 col-tiles
    const dim3 ag(NN/128, HH, BB);

    // ---- prep: split emb/gelu(emb)/weights ----
    prep_k<<<2688, 256>>>(emb, Wq0, Wk0, Wv0, Wo0, Wq1, Wk1, Wv1, Wo1, ff_W1, ff_W2);

    // ---- MHA 0 ----
    gemm2_k<128,false,false,false,true ><<<g3, 256, SM128>>>(emb_h, emb_l, W_h, W_l, QKV_h, QKV_l, nullptr, nullptr, nullptr);
    attn3_k<<<ag, 256, ATTN_SMEM>>>(QKV_h, QKV_l, pA_h, pA_l);
    gemm2_k<64 ,true ,false,false,true ><<<g1, 256, SM64>>>(pA_h, pA_l, W_h + 3*DD*DD, W_l + 3*DD*DD, pB_h, pB_l, nullptr, nullptr, nullptr);

    // ---- MHA 1 ----
    gemm2_k<128,false,false,false,true ><<<g3, 256, SM128>>>(pB_h, pB_l, W_h + 4*DD*DD, W_l + 4*DD*DD, QKV_h, QKV_l, nullptr, nullptr, nullptr);
    attn3_k<<<ag, 256, ATTN_SMEM>>>(QKV_h, QKV_l, pA_h, pA_l);
    gemm2_k<64 ,false,false,false,false><<<g1, 256, SM64>>>(pA_h, pA_l, W_h + 7*DD*DD, W_l + 7*DD*DD, nullptr, nullptr, X32, nullptr, nullptr);

    // ---- aggregation ----
    aggr_k<<<BB, 256>>>(X32, res_W, res_b, ff_W1, tv);

    // ---- FF ----
    gemm2_k<64 ,true ,true ,true ,true ><<<g1, 256, SM64>>>(gemb_h, gemb_l, W_h + 8*DD*DD, W_l + 8*DD*DD, pB_h, pB_l, nullptr, ff_b1, tv);
    gemm2_k<64 ,false,true ,false,false><<<g1, 256, SM64>>>(pB_h, pB_l, W_h + 9*DD*DD, W_l + 9*DD*DD, nullptr, nullptr, X32, ff_b2, nullptr);

    // ---- prototypes + scoring ----
    proto_k<<<BB, 256>>>(X32, labels, P, cnt);
    score_k<<<dim3(NN/8, BB), 256>>>(X32, P, cnt, labels, out);
}